// round 6
// baseline (speedup 1.0000x reference)
#include <cuda_runtime.h>
#include <cuda_bf16.h>
#include <cstdint>

// Problem constants
#define B_    32
#define U_    4096
#define D_    512
#define H_    4
#define HD_   128
#define CK_   31
#define CF_   32
#define AU_   512

#define UC    128            // u rows per CTA chunk
#define NC    (U_ / UC)      // 32 chunks per batch

// ---------------- scratch (device globals) ----------------------------------
__device__ float g_KEFF[CK_ * H_];
__device__ float g_V[B_ * H_ * D_];
__device__ float g_LB[(size_t)B_ * U_ * H_];                // location bias [b][u][h]
__device__ float g_P[(size_t)B_ * U_ * H_];                 // exp(energy), [b][u][h]
__device__ float g_CTXP[(size_t)B_ * NC * H_ * D_];         // per-chunk ctx partials
__device__ float g_SP[B_ * NC * H_];                        // per-chunk sum of p
__device__ float g_CTX[B_ * H_ * D_];                       // normalized context
__device__ float g_S[B_ * H_];                              // global sums
__device__ float g_OUTP[4 * B_ * AU_];                      // out GEMM partials

// ---------------- kernel 0: effective conv kernel ---------------------------
__global__ void keff_kernel(const float* __restrict__ ck,
                            const float* __restrict__ Wloc)
{
    int i = threadIdx.x;
    if (i < CK_ * H_) {
        int k = i >> 2, h = i & 3;
        float s = 0.f;
        #pragma unroll
        for (int f = 0; f < CF_; f++) s += ck[k * CF_ + f] * Wloc[f * H_ + h];
        g_KEFF[i] = s;
    }
}

// ---------------- kernel 1: phi & v -----------------------------------------
__global__ void phiv_kernel(const float* __restrict__ dec,
                            const float* __restrict__ Wphi,
                            const float* __restrict__ bphi,
                            const float* __restrict__ Wpsi)
{
    int bh = blockIdx.x;
    int b = bh >> 2, h = bh & 3;
    __shared__ float dec_sm[D_];
    __shared__ float phi_part[2][HD_];
    __shared__ float phi_sm[HD_];
    int tid = threadIdx.x;   // 256

    for (int i = tid; i < D_; i += 256) dec_sm[i] = dec[(size_t)b * D_ + i];
    __syncthreads();

    {
        int k = tid & 127, sl = tid >> 7;
        const float* w = Wphi + (size_t)h * D_ * HD_ + (size_t)sl * 256 * HD_ + k;
        const float* ds = dec_sm + sl * 256;
        float a0 = 0.f, a1 = 0.f, a2 = 0.f, a3 = 0.f;
        #pragma unroll 8
        for (int d = 0; d < 256; d += 4) {
            a0 += ds[d + 0] * w[(size_t)(d + 0) * HD_];
            a1 += ds[d + 1] * w[(size_t)(d + 1) * HD_];
            a2 += ds[d + 2] * w[(size_t)(d + 2) * HD_];
            a3 += ds[d + 3] * w[(size_t)(d + 3) * HD_];
        }
        phi_part[sl][k] = (a0 + a1) + (a2 + a3);
    }
    __syncthreads();
    if (tid < HD_)
        phi_sm[tid] = phi_part[0][tid] + phi_part[1][tid] + bphi[h * HD_ + tid];
    __syncthreads();

    for (int e = tid; e < D_; e += 256) {
        const float4* wp = reinterpret_cast<const float4*>(
            Wpsi + ((size_t)h * D_ + e) * HD_);
        float vv = 0.f;
        #pragma unroll 8
        for (int k4 = 0; k4 < HD_ / 4; k4++) {
            float4 ww = wp[k4];
            vv += ww.x * phi_sm[4 * k4 + 0] + ww.y * phi_sm[4 * k4 + 1]
                + ww.z * phi_sm[4 * k4 + 2] + ww.w * phi_sm[4 * k4 + 3];
        }
        g_V[(size_t)bh * D_ + e] = vv;
    }
}

// ---------------- kernel 2: location bias for all (b,u,h) -------------------
// grid (4, B), block 256; each block covers 1024 u's
__global__ void lb_kernel(const float* __restrict__ prev)
{
    __shared__ float prevs[1024 + CK_ - 1];
    __shared__ float keffs[CK_ * H_];
    int z = blockIdx.x, b = blockIdx.y;
    int tid = threadIdx.x;
    int ubase = z * 1024;

    for (int i = tid; i < 1024 + CK_ - 1; i += 256) {
        int gu = ubase + i - 15;
        prevs[i] = (gu >= 0 && gu < U_) ? prev[(size_t)b * U_ + gu] : 0.f;
    }
    if (tid < CK_ * H_) keffs[tid] = g_KEFF[tid];
    __syncthreads();

    float4* outp = reinterpret_cast<float4*>(g_LB + ((size_t)b * U_ + ubase) * H_);
    #pragma unroll
    for (int q = 0; q < 4; q++) {
        int ul = tid + 256 * q;
        float l0 = 0.f, l1 = 0.f, l2 = 0.f, l3 = 0.f;
        #pragma unroll
        for (int k = 0; k < CK_; k++) {
            float pv = prevs[ul + k];
            l0 += pv * keffs[k * H_ + 0];
            l1 += pv * keffs[k * H_ + 1];
            l2 += pv * keffs[k * H_ + 2];
            l3 += pv * keffs[k * H_ + 3];
        }
        outp[ul] = make_float4(l0, l1, l2, l3);
    }
}

// ---------------- kernel 3 (PROFILED SLOT): fused energy+exp+context --------
// grid (NC, B), block 256, 2 CTAs/SM. No TMA, no main-loop barriers.
// Warp-pair split: pair = warp>>1 owns rows (pair + 4t); j = warp&1 owns
// heads {2j, 2j+1}. Row x double-buffered in registers; ctx in registers.
__global__ void __launch_bounds__(256, 2)
fused_kernel(const float* __restrict__ enc)
{
    __shared__ float pall[UC * H_];         // [uu][h]
    __shared__ float ctxred[4][H_][D_];     // per-pair ctx partials (32 KB)

    int tid  = threadIdx.x;
    int warp = tid >> 5, lane = tid & 31;
    int pair = warp >> 1, j = warp & 1;
    int b  = blockIdx.y;
    int u0 = blockIdx.x * UC;

    // v for this warp's 2 heads
    float4 v[2][4];
    #pragma unroll
    for (int g = 0; g < 2; g++) {
        const float4* vp = reinterpret_cast<const float4*>(
            g_V + (size_t)(b * H_ + 2 * j + g) * D_);
        #pragma unroll
        for (int i = 0; i < 4; i++) v[g][i] = __ldg(vp + lane + 32 * i);
    }

    float4 ctx[2][4];
    #pragma unroll
    for (int g = 0; g < 2; g++)
        #pragma unroll
        for (int i = 0; i < 4; i++) ctx[g][i] = make_float4(0.f, 0.f, 0.f, 0.f);

    const float4* ebase = reinterpret_cast<const float4*>(
        enc + ((size_t)b * U_ + u0) * D_);
    const float2* lbp = reinterpret_cast<const float2*>(
        g_LB + ((size_t)b * U_ + u0) * H_ + 2 * j);

    float4 xb[2][4];
    // preload first row (r = pair)
    {
        const float4* rp = ebase + (size_t)pair * (D_ / 4) + lane;
        #pragma unroll
        for (int i = 0; i < 4; i++) xb[0][i] = __ldg(rp + 32 * i);
    }

    for (int t = 0; t < UC / 4; t++) {
        int cur = t & 1;
        int r = pair + 4 * t;
        // issue next row's loads FIRST (hide latency behind this row's math)
        if (t < UC / 4 - 1) {
            const float4* rp = ebase + (size_t)(r + 4) * (D_ / 4) + lane;
            #pragma unroll
            for (int i = 0; i < 4; i++) xb[cur ^ 1][i] = __ldg(rp + 32 * i);
        }

        // dot products for 2 heads
        float a0 = 0.f, a1 = 0.f;
        #pragma unroll
        for (int i = 0; i < 4; i++) {
            float4 x = xb[cur][i];
            a0 += x.x * v[0][i].x + x.y * v[0][i].y
                + x.z * v[0][i].z + x.w * v[0][i].w;
            a1 += x.x * v[1][i].x + x.y * v[1][i].y
                + x.z * v[1][i].z + x.w * v[1][i].w;
        }
        // xor butterfly: every lane ends with the full sum
        #pragma unroll
        for (int off = 16; off; off >>= 1) {
            a0 += __shfl_xor_sync(0xffffffffu, a0, off);
            a1 += __shfl_xor_sync(0xffffffffu, a1, off);
        }
        float2 lb = __ldg(lbp + r * 2);      // (H_/2 float2 per row) -> stride 2
        float p0 = __expf(a0 + lb.x);
        float p1 = __expf(a1 + lb.y);
        if (lane == 0)
            *reinterpret_cast<float2*>(pall + r * H_ + 2 * j) =
                make_float2(p0, p1);

        // context accumulate from the same registers
        #pragma unroll
        for (int i = 0; i < 4; i++) {
            float4 x = xb[cur][i];
            ctx[0][i].x += p0 * x.x; ctx[0][i].y += p0 * x.y;
            ctx[0][i].z += p0 * x.z; ctx[0][i].w += p0 * x.w;
            ctx[1][i].x += p1 * x.x; ctx[1][i].y += p1 * x.y;
            ctx[1][i].z += p1 * x.z; ctx[1][i].w += p1 * x.w;
        }
    }

    // dump per-warp ctx to smem
    #pragma unroll
    for (int g = 0; g < 2; g++) {
        float4* cr = reinterpret_cast<float4*>(ctxred[pair][2 * j + g]);
        #pragma unroll
        for (int i = 0; i < 4; i++) cr[lane + 32 * i] = ctx[g][i];
    }
    __syncthreads();

    size_t chunk = (size_t)b * NC + blockIdx.x;

    // reduce 4 pairs -> g_CTXP  (2048 (h,e) slots, 8 per thread)
    #pragma unroll
    for (int q = 0; q < 8; q++) {
        int idx = tid + 256 * q;           // [0, 2048)
        int h = idx >> 9, e = idx & 511;
        float s = ctxred[0][h][e] + ctxred[1][h][e]
                + ctxred[2][h][e] + ctxred[3][h][e];
        g_CTXP[(chunk * H_ + h) * D_ + e] = s;
    }

    // per-chunk sum of p
    if (warp < H_) {
        float sp = pall[lane * H_ + warp] + pall[(lane + 32) * H_ + warp]
                 + pall[(lane + 64) * H_ + warp] + pall[(lane + 96) * H_ + warp];
        #pragma unroll
        for (int off = 16; off; off >>= 1)
            sp += __shfl_xor_sync(0xffffffffu, sp, off);
        if (lane == 0) g_SP[chunk * H_ + warp] = sp;
    }

    // raw p -> g_P ([b][u][h])
    #pragma unroll
    for (int jj = 0; jj < 2; jj++) {
        int idx = tid + 256 * jj;          // [0,512) == [uu][h]
        g_P[((size_t)b * U_ + u0) * H_ + idx] = pall[idx];
    }
}

// ---------------- combine partials per (b,h) --------------------------------
__global__ void combine_kernel()
{
    int h = blockIdx.x, b = blockIdx.y;
    int tid = threadIdx.x;
    __shared__ float S_sm;

    if (tid < 32) {
        float sc = g_SP[((size_t)b * NC + tid) * H_ + h];
        #pragma unroll
        for (int off = 16; off; off >>= 1)
            sc += __shfl_xor_sync(0xffffffffu, sc, off);
        if (tid == 0) {
            S_sm = sc;
            g_S[b * H_ + h] = sc;
        }
    }
    __syncthreads();
    float invS = 1.f / S_sm;

    const float* base = g_CTXP + ((size_t)b * NC * H_ + h) * D_ + tid;
    float a = 0.f;
    #pragma unroll 8
    for (int c = 0; c < NC; c++)
        a += base[(size_t)c * H_ * D_];
    g_CTX[(size_t)(b * H_ + h) * D_ + tid] = a * invS;
}

// ---------------- attention weights (mean over heads) -----------------------
__global__ void aw_kernel(float* __restrict__ out)
{
    int z = blockIdx.x, b = blockIdx.y;
    float i0 = 0.25f / g_S[b * H_ + 0];
    float i1 = 0.25f / g_S[b * H_ + 1];
    float i2 = 0.25f / g_S[b * H_ + 2];
    float i3 = 0.25f / g_S[b * H_ + 3];
    const float4* p = reinterpret_cast<const float4*>(
        g_P + ((size_t)b * U_ + z * 1024) * H_);
    float* o = out + (size_t)B_ * AU_ + (size_t)b * U_ + z * 1024;
    for (int u = threadIdx.x; u < 1024; u += 256) {
        float4 v = p[u];
        o[u] = v.x * i0 + v.y * i1 + v.z * i2 + v.w * i3;
    }
}

// ---------------- out GEMM partials ------------------------------------------
__global__ void outp_kernel(const float* __restrict__ Wout)
{
    extern __shared__ float c_sm[];   // [b][i] : 32 x 512
    int cg = blockIdx.x, s = blockIdx.y;
    int tid = threadIdx.x;
    int col = cg * 32 + (tid & 31);
    int bg  = tid >> 5;

    for (int k = tid; k < 32 * 512; k += 256) {
        int bb = k >> 9, i = k & 511;
        c_sm[k] = g_CTX[(size_t)bb * (H_ * D_) + s * 512 + i];
    }
    __syncthreads();

    float acc0 = 0.f, acc1 = 0.f, acc2 = 0.f, acc3 = 0.f;
    const float* wp = Wout + (size_t)s * 512 * AU_ + col;
    const float* c0 = c_sm + (4 * bg + 0) * 512;
    const float* c1 = c_sm + (4 * bg + 1) * 512;
    const float* c2 = c_sm + (4 * bg + 2) * 512;
    const float* c3 = c_sm + (4 * bg + 3) * 512;
    #pragma unroll 8
    for (int i = 0; i < 512; i++) {
        float w = wp[(size_t)i * AU_];
        acc0 += c0[i] * w;
        acc1 += c1[i] * w;
        acc2 += c2[i] * w;
        acc3 += c3[i] * w;
    }
    float* op = g_OUTP + (size_t)s * B_ * AU_ + col;
    op[(4 * bg + 0) * AU_] = acc0;
    op[(4 * bg + 1) * AU_] = acc1;
    op[(4 * bg + 2) * AU_] = acc2;
    op[(4 * bg + 3) * AU_] = acc3;
}

// ---------------- out final --------------------------------------------------
__global__ void outf_kernel(const float* __restrict__ bout,
                            float* __restrict__ out)
{
    int b = blockIdx.x, t = threadIdx.x;
    float v = bout[t]
            + g_OUTP[(0 * B_ + b) * AU_ + t] + g_OUTP[(1 * B_ + b) * AU_ + t]
            + g_OUTP[(2 * B_ + b) * AU_ + t] + g_OUTP[(3 * B_ + b) * AU_ + t];
    out[(size_t)b * AU_ + t] = v;
}

// ---------------------------------------------------------------------------
extern "C" void kernel_launch(void* const* d_in, const int* in_sizes, int n_in,
                              void* d_out, int out_size)
{
    const float* dec   = (const float*)d_in[0];
    const float* enc   = (const float*)d_in[1];
    const float* prev  = (const float*)d_in[2];
    const float* Wphi  = (const float*)d_in[3];
    const float* bphi  = (const float*)d_in[4];
    const float* Wpsi  = (const float*)d_in[5];
    // d_in[6] = bpsi: constant along u per (b,h) -> softmax-invariant, unused
    const float* ck    = (const float*)d_in[7];
    const float* Wloc  = (const float*)d_in[8];
    const float* Wout  = (const float*)d_in[9];
    const float* bout  = (const float*)d_in[10];
    float* out = (float*)d_out;

    cudaFuncSetAttribute(outp_kernel,
                         cudaFuncAttributeMaxDynamicSharedMemorySize,
                         32 * 512 * 4);

    keff_kernel<<<1, 128>>>(ck, Wloc);                      // idx 0
    phiv_kernel<<<B_ * H_, 256>>>(dec, Wphi, bphi, Wpsi);   // idx 1
    lb_kernel<<<dim3(4, B_), 256>>>(prev);                  // idx 2
    fused_kernel<<<dim3(NC, B_), 256>>>(enc);               // idx 3 <- profiled
    combine_kernel<<<dim3(H_, B_), 512>>>();                // idx 4
    aw_kernel<<<dim3(4, B_), 256>>>(out);                   // idx 5
    outp_kernel<<<dim3(16, 4), 256, 32 * 512 * 4>>>(Wout);  // idx 6
    outf_kernel<<<B_, 512>>>(bout, out);                    // idx 7
}

// round 7
// speedup vs baseline: 1.4078x; 1.4078x over previous
#include <cuda_runtime.h>
#include <cuda_bf16.h>
#include <cstdint>

// Problem constants
#define B_    32
#define U_    4096
#define D_    512
#define H_    4
#define HD_   128
#define CK_   31
#define CF_   32
#define AU_   512

#define UC    128            // u rows per CTA chunk
#define NC    (U_ / UC)      // 32 chunks per batch
#define ST    8              // rows per pipeline stage
#define NSUB  (UC / ST)      // 16

// ---------------- scratch (device globals) ----------------------------------
__device__ float g_KEFF[CK_ * H_];
__device__ float g_V[B_ * H_ * D_];
__device__ float g_LB[(size_t)B_ * U_ * H_];                // location bias [b][u][h]
__device__ float g_P[(size_t)B_ * U_ * H_];                 // exp(energy), [b][u][h]
__device__ float g_CTXP[(size_t)B_ * NC * H_ * D_];         // per-chunk ctx partials
__device__ float g_SP[B_ * NC * H_];                        // per-chunk sum of p
__device__ float g_CTX[B_ * H_ * D_];                       // normalized context
__device__ float g_S[B_ * H_];                              // global sums
__device__ float g_OUTP[4 * B_ * AU_];                      // out GEMM partials

// ---------------- PTX helpers -----------------------------------------------
__device__ __forceinline__ uint32_t smem_u32(const void* p) {
    uint32_t a;
    asm("{ .reg .u64 t; cvta.to.shared.u64 t, %1; cvt.u32.u64 %0, t; }"
        : "=r"(a) : "l"(p));
    return a;
}
__device__ __forceinline__ void cp_async16(uint32_t dst, const void* src) {
    asm volatile("cp.async.cg.shared.global [%0], [%1], 16;"
                 :: "r"(dst), "l"(src) : "memory");
}
__device__ __forceinline__ void cp_commit() {
    asm volatile("cp.async.commit_group;" ::: "memory");
}
template <int N>
__device__ __forceinline__ void cp_wait() {
    asm volatile("cp.async.wait_group %0;" :: "n"(N) : "memory");
}

// ---------------- kernel 0: effective conv kernel ---------------------------
__global__ void keff_kernel(const float* __restrict__ ck,
                            const float* __restrict__ Wloc)
{
    int i = threadIdx.x;
    if (i < CK_ * H_) {
        int k = i >> 2, h = i & 3;
        float s = 0.f;
        #pragma unroll
        for (int f = 0; f < CF_; f++) s += ck[k * CF_ + f] * Wloc[f * H_ + h];
        g_KEFF[i] = s;
    }
}

// ---------------- kernel 1: phi & v -----------------------------------------
__global__ void phiv_kernel(const float* __restrict__ dec,
                            const float* __restrict__ Wphi,
                            const float* __restrict__ bphi,
                            const float* __restrict__ Wpsi)
{
    int bh = blockIdx.x;
    int b = bh >> 2, h = bh & 3;
    __shared__ float dec_sm[D_];
    __shared__ float phi_part[2][HD_];
    __shared__ float phi_sm[HD_];
    int tid = threadIdx.x;   // 256

    for (int i = tid; i < D_; i += 256) dec_sm[i] = dec[(size_t)b * D_ + i];
    __syncthreads();

    {
        int k = tid & 127, sl = tid >> 7;
        const float* w = Wphi + (size_t)h * D_ * HD_ + (size_t)sl * 256 * HD_ + k;
        const float* ds = dec_sm + sl * 256;
        float a0 = 0.f, a1 = 0.f, a2 = 0.f, a3 = 0.f;
        #pragma unroll 8
        for (int d = 0; d < 256; d += 4) {
            a0 += ds[d + 0] * w[(size_t)(d + 0) * HD_];
            a1 += ds[d + 1] * w[(size_t)(d + 1) * HD_];
            a2 += ds[d + 2] * w[(size_t)(d + 2) * HD_];
            a3 += ds[d + 3] * w[(size_t)(d + 3) * HD_];
        }
        phi_part[sl][k] = (a0 + a1) + (a2 + a3);
    }
    __syncthreads();
    if (tid < HD_)
        phi_sm[tid] = phi_part[0][tid] + phi_part[1][tid] + bphi[h * HD_ + tid];
    __syncthreads();

    for (int e = tid; e < D_; e += 256) {
        const float4* wp = reinterpret_cast<const float4*>(
            Wpsi + ((size_t)h * D_ + e) * HD_);
        float vv = 0.f;
        #pragma unroll 8
        for (int k4 = 0; k4 < HD_ / 4; k4++) {
            float4 ww = wp[k4];
            vv += ww.x * phi_sm[4 * k4 + 0] + ww.y * phi_sm[4 * k4 + 1]
                + ww.z * phi_sm[4 * k4 + 2] + ww.w * phi_sm[4 * k4 + 3];
        }
        g_V[(size_t)bh * D_ + e] = vv;
    }
}

// ---------------- kernel 2: location bias for all (b,u,h) -------------------
__global__ void lb_kernel(const float* __restrict__ prev)
{
    __shared__ float prevs[1024 + CK_ - 1];
    __shared__ float keffs[CK_ * H_];
    int z = blockIdx.x, b = blockIdx.y;
    int tid = threadIdx.x;
    int ubase = z * 1024;

    for (int i = tid; i < 1024 + CK_ - 1; i += 256) {
        int gu = ubase + i - 15;
        prevs[i] = (gu >= 0 && gu < U_) ? prev[(size_t)b * U_ + gu] : 0.f;
    }
    if (tid < CK_ * H_) keffs[tid] = g_KEFF[tid];
    __syncthreads();

    float4* outp = reinterpret_cast<float4*>(g_LB + ((size_t)b * U_ + ubase) * H_);
    #pragma unroll
    for (int q = 0; q < 4; q++) {
        int ul = tid + 256 * q;
        float l0 = 0.f, l1 = 0.f, l2 = 0.f, l3 = 0.f;
        #pragma unroll
        for (int k = 0; k < CK_; k++) {
            float pv = prevs[ul + k];
            l0 += pv * keffs[k * H_ + 0];
            l1 += pv * keffs[k * H_ + 1];
            l2 += pv * keffs[k * H_ + 2];
            l3 += pv * keffs[k * H_ + 3];
        }
        outp[ul] = make_float4(l0, l1, l2, l3);
    }
}

// ---------------- kernel 3 (PROFILED): fused energy+exp+context -------------
// grid (NC, B), 256 threads, 3 CTAs/SM target.
// cp.async double-buffered 8-row tiles in smem; warp = rg*?; one head/warp:
//   h = warp&3, rg = warp>>2; warp handles rows rg*4..rg*4+3 of each subtile
//   for head h. v: 16 regs, ctx: 16 regs.
// dynamic smem floats:
//   [0)      tiles  : 2*ST*D = 8192
//   [8192)   ctxred : 2*H*D  = 4096
//   [12288)  pall   : UC*H   = 512
//   [12800)  lbs    : UC*H   = 512
#define SMEM_F_FLOATS 13312
#define SMEM_F_BYTES (SMEM_F_FLOATS * 4)

__global__ void __launch_bounds__(256, 3)
fused_kernel(const float* __restrict__ enc)
{
    extern __shared__ float smem[];
    float* tiles  = smem;                 // [2][ST*D]
    float* ctxred = smem + 8192;          // [rg][h][D]
    float* pall   = smem + 12288;         // [uu][h]
    float* lbs    = smem + 12800;         // [uu][h]

    int tid  = threadIdx.x;
    int warp = tid >> 5, lane = tid & 31;
    int h = warp & 3, rg = warp >> 2;
    int b  = blockIdx.y;
    int u0 = blockIdx.x * UC;

    const float* enc_base = enc + ((size_t)b * U_ + u0) * D_;
    uint32_t tiles_s = smem_u32(tiles);

    // prologue: stage subtiles 0 and 1
    #pragma unroll
    for (int s = 0; s < 2; s++) {
        uint32_t dst = tiles_s + s * (ST * D_ * 4);
        const float* src = enc_base + s * ST * D_;
        #pragma unroll
        for (int q = 0; q < 4; q++) {
            int idx = tid + 256 * q;      // 16B chunks
            cp_async16(dst + idx * 16, src + idx * 4);
        }
        cp_commit();
    }

    // stage lb for the chunk
    #pragma unroll
    for (int q = 0; q < 2; q++) {
        int idx = tid + 256 * q;
        lbs[idx] = g_LB[((size_t)b * U_ + u0) * H_ + idx];
    }

    // v for this warp's head
    float4 v[4];
    {
        const float4* vp = reinterpret_cast<const float4*>(
            g_V + (size_t)(b * H_ + h) * D_);
        #pragma unroll
        for (int i = 0; i < 4; i++) v[i] = __ldg(vp + lane + 32 * i);
    }

    float4 ctx[4];
    #pragma unroll
    for (int i = 0; i < 4; i++) ctx[i] = make_float4(0.f, 0.f, 0.f, 0.f);

    for (int s = 0; s < NSUB; s++) {
        if (s < NSUB - 1) cp_wait<1>(); else cp_wait<0>();
        __syncthreads();
        const float* tile = tiles + (s & 1) * (ST * D_);

        #pragma unroll
        for (int t = 0; t < 4; t++) {
            int r = rg * 4 + t;
            int uu = s * ST + r;
            const float4* row = reinterpret_cast<const float4*>(tile + r * D_);
            float4 x0 = row[lane];
            float4 x1 = row[lane + 32];
            float4 x2 = row[lane + 64];
            float4 x3 = row[lane + 96];
            float a = x0.x * v[0].x + x0.y * v[0].y + x0.z * v[0].z + x0.w * v[0].w;
            a += x1.x * v[1].x + x1.y * v[1].y + x1.z * v[1].z + x1.w * v[1].w;
            a += x2.x * v[2].x + x2.y * v[2].y + x2.z * v[2].z + x2.w * v[2].w;
            a += x3.x * v[3].x + x3.y * v[3].y + x3.z * v[3].z + x3.w * v[3].w;
            #pragma unroll
            for (int off = 16; off; off >>= 1)
                a += __shfl_xor_sync(0xffffffffu, a, off);
            float p = __expf(a + lbs[uu * H_ + h]);
            if (lane == 0) pall[uu * H_ + h] = p;
            ctx[0].x += p * x0.x; ctx[0].y += p * x0.y;
            ctx[0].z += p * x0.z; ctx[0].w += p * x0.w;
            ctx[1].x += p * x1.x; ctx[1].y += p * x1.y;
            ctx[1].z += p * x1.z; ctx[1].w += p * x1.w;
            ctx[2].x += p * x2.x; ctx[2].y += p * x2.y;
            ctx[2].z += p * x2.z; ctx[2].w += p * x2.w;
            ctx[3].x += p * x3.x; ctx[3].y += p * x3.y;
            ctx[3].z += p * x3.z; ctx[3].w += p * x3.w;
        }
        __syncthreads();   // done reading this buffer

        if (s + 2 < NSUB) {
            uint32_t dst = tiles_s + (s & 1) * (ST * D_ * 4);
            const float* src = enc_base + (s + 2) * ST * D_;
            #pragma unroll
            for (int q = 0; q < 4; q++) {
                int idx = tid + 256 * q;
                cp_async16(dst + idx * 16, src + idx * 4);
            }
            cp_commit();
        }
    }

    // merge the two row-groups per head
    {
        float4* cr = reinterpret_cast<float4*>(ctxred + (rg * H_ + h) * D_);
        #pragma unroll
        for (int i = 0; i < 4; i++) cr[lane + 32 * i] = ctx[i];
    }
    __syncthreads();

    size_t chunk = (size_t)b * NC + blockIdx.x;

    #pragma unroll
    for (int q = 0; q < 8; q++) {
        int idx = tid + 256 * q;           // [0, 2048) == [h][e]
        int hh = idx >> 9, e = idx & 511;
        g_CTXP[(chunk * H_ + hh) * D_ + e] =
            ctxred[hh * D_ + e] + ctxred[(H_ + hh) * D_ + e];
    }

    // per-chunk sum of p (warp hh reduces pall[:][hh])
    if (warp < H_) {
        float sp = pall[lane * H_ + warp] + pall[(lane + 32) * H_ + warp]
                 + pall[(lane + 64) * H_ + warp] + pall[(lane + 96) * H_ + warp];
        #pragma unroll
        for (int off = 16; off; off >>= 1)
            sp += __shfl_xor_sync(0xffffffffu, sp, off);
        if (lane == 0) g_SP[chunk * H_ + warp] = sp;
    }

    // raw p -> g_P ([b][u][h])
    #pragma unroll
    for (int jj = 0; jj < 2; jj++) {
        int idx = tid + 256 * jj;
        g_P[((size_t)b * U_ + u0) * H_ + idx] = pall[idx];
    }
}

// ---------------- combine partials per (b,h) --------------------------------
__global__ void combine_kernel()
{
    int h = blockIdx.x, b = blockIdx.y;
    int tid = threadIdx.x;
    __shared__ float S_sm;

    if (tid < 32) {
        float sc = g_SP[((size_t)b * NC + tid) * H_ + h];
        #pragma unroll
        for (int off = 16; off; off >>= 1)
            sc += __shfl_xor_sync(0xffffffffu, sc, off);
        if (tid == 0) {
            S_sm = sc;
            g_S[b * H_ + h] = sc;
        }
    }
    __syncthreads();
    float invS = 1.f / S_sm;

    const float* base = g_CTXP + ((size_t)b * NC * H_ + h) * D_ + tid;
    float a = 0.f;
    #pragma unroll 8
    for (int c = 0; c < NC; c++)
        a += base[(size_t)c * H_ * D_];
    g_CTX[(size_t)(b * H_ + h) * D_ + tid] = a * invS;
}

// ---------------- attention weights (mean over heads) -----------------------
__global__ void aw_kernel(float* __restrict__ out)
{
    int z = blockIdx.x, b = blockIdx.y;
    float i0 = 0.25f / g_S[b * H_ + 0];
    float i1 = 0.25f / g_S[b * H_ + 1];
    float i2 = 0.25f / g_S[b * H_ + 2];
    float i3 = 0.25f / g_S[b * H_ + 3];
    const float4* p = reinterpret_cast<const float4*>(
        g_P + ((size_t)b * U_ + z * 1024) * H_);
    float* o = out + (size_t)B_ * AU_ + (size_t)b * U_ + z * 1024;
    for (int u = threadIdx.x; u < 1024; u += 256) {
        float4 v = p[u];
        o[u] = v.x * i0 + v.y * i1 + v.z * i2 + v.w * i3;
    }
}

// ---------------- out GEMM partials ------------------------------------------
__global__ void outp_kernel(const float* __restrict__ Wout)
{
    extern __shared__ float c_sm[];   // [b][i] : 32 x 512
    int cg = blockIdx.x, s = blockIdx.y;
    int tid = threadIdx.x;
    int col = cg * 32 + (tid & 31);
    int bg  = tid >> 5;

    for (int k = tid; k < 32 * 512; k += 256) {
        int bb = k >> 9, i = k & 511;
        c_sm[k] = g_CTX[(size_t)bb * (H_ * D_) + s * 512 + i];
    }
    __syncthreads();

    float acc0 = 0.f, acc1 = 0.f, acc2 = 0.f, acc3 = 0.f;
    const float* wp = Wout + (size_t)s * 512 * AU_ + col;
    const float* c0 = c_sm + (4 * bg + 0) * 512;
    const float* c1 = c_sm + (4 * bg + 1) * 512;
    const float* c2 = c_sm + (4 * bg + 2) * 512;
    const float* c3 = c_sm + (4 * bg + 3) * 512;
    #pragma unroll 8
    for (int i = 0; i < 512; i++) {
        float w = wp[(size_t)i * AU_];
        acc0 += c0[i] * w;
        acc1 += c1[i] * w;
        acc2 += c2[i] * w;
        acc3 += c3[i] * w;
    }
    float* op = g_OUTP + (size_t)s * B_ * AU_ + col;
    op[(4 * bg + 0) * AU_] = acc0;
    op[(4 * bg + 1) * AU_] = acc1;
    op[(4 * bg + 2) * AU_] = acc2;
    op[(4 * bg + 3) * AU_] = acc3;
}

// ---------------- out final --------------------------------------------------
__global__ void outf_kernel(const float* __restrict__ bout,
                            float* __restrict__ out)
{
    int b = blockIdx.x, t = threadIdx.x;
    float v = bout[t]
            + g_OUTP[(0 * B_ + b) * AU_ + t] + g_OUTP[(1 * B_ + b) * AU_ + t]
            + g_OUTP[(2 * B_ + b) * AU_ + t] + g_OUTP[(3 * B_ + b) * AU_ + t];
    out[(size_t)b * AU_ + t] = v;
}

// ---------------------------------------------------------------------------
extern "C" void kernel_launch(void* const* d_in, const int* in_sizes, int n_in,
                              void* d_out, int out_size)
{
    const float* dec   = (const float*)d_in[0];
    const float* enc   = (const float*)d_in[1];
    const float* prev  = (const float*)d_in[2];
    const float* Wphi  = (const float*)d_in[3];
    const float* bphi  = (const float*)d_in[4];
    const float* Wpsi  = (const float*)d_in[5];
    // d_in[6] = bpsi: constant along u per (b,h) -> softmax-invariant, unused
    const float* ck    = (const float*)d_in[7];
    const float* Wloc  = (const float*)d_in[8];
    const float* Wout  = (const float*)d_in[9];
    const float* bout  = (const float*)d_in[10];
    float* out = (float*)d_out;

    cudaFuncSetAttribute(fused_kernel,
                         cudaFuncAttributeMaxDynamicSharedMemorySize,
                         SMEM_F_BYTES);
    cudaFuncSetAttribute(outp_kernel,
                         cudaFuncAttributeMaxDynamicSharedMemorySize,
                         32 * 512 * 4);

    keff_kernel<<<1, 128>>>(ck, Wloc);                      // idx 0
    phiv_kernel<<<B_ * H_, 256>>>(dec, Wphi, bphi, Wpsi);   // idx 1
    lb_kernel<<<dim3(4, B_), 256>>>(prev);                  // idx 2
    fused_kernel<<<dim3(NC, B_), 256, SMEM_F_BYTES>>>(enc); // idx 3 <- profiled
    combine_kernel<<<dim3(H_, B_), 512>>>();                // idx 4
    aw_kernel<<<dim3(4, B_), 256>>>(out);                   // idx 5
    outp_kernel<<<dim3(16, 4), 256, 32 * 512 * 4>>>(Wout);  // idx 6
    outf_kernel<<<B_, 512>>>(bout, out);                    // idx 7
}

// round 8
// speedup vs baseline: 1.5712x; 1.1161x over previous
#include <cuda_runtime.h>
#include <cuda_bf16.h>
#include <cstdint>

// Problem constants
#define B_    32
#define U_    4096
#define D_    512
#define H_    4
#define HD_   128
#define CK_   31
#define CF_   32
#define AU_   512

#define UC    128            // u rows per CTA chunk
#define NC    (U_ / UC)      // 32 chunks per batch
#define ST    8              // rows per pipeline stage
#define NSUB  (UC / ST)      // 16

// ---------------- scratch (device globals) ----------------------------------
__device__ float g_V[B_ * H_ * D_];
__device__ float g_LB[(size_t)B_ * U_ * H_];                // location bias [b][u][h]
__device__ float g_P[(size_t)B_ * U_ * H_];                 // exp(energy), [b][u][h]
__device__ float g_CTXP[(size_t)B_ * NC * H_ * D_];         // per-chunk ctx partials
__device__ float g_SP[B_ * NC * H_];                        // per-chunk sum of p
__device__ float g_CTX[B_ * H_ * D_];                       // normalized context
__device__ float g_OUTP[4 * B_ * AU_];                      // out GEMM partials

// ---------------- PTX helpers -----------------------------------------------
__device__ __forceinline__ uint32_t smem_u32(const void* p) {
    uint32_t a;
    asm("{ .reg .u64 t; cvta.to.shared.u64 t, %1; cvt.u32.u64 %0, t; }"
        : "=r"(a) : "l"(p));
    return a;
}
__device__ __forceinline__ void cp_async16(uint32_t dst, const void* src) {
    asm volatile("cp.async.cg.shared.global [%0], [%1], 16;"
                 :: "r"(dst), "l"(src) : "memory");
}
__device__ __forceinline__ void cp_commit() {
    asm volatile("cp.async.commit_group;" ::: "memory");
}
template <int N>
__device__ __forceinline__ void cp_wait() {
    asm volatile("cp.async.wait_group %0;" :: "n"(N) : "memory");
}
__device__ __forceinline__ void fma2(unsigned long long& d,
                                     unsigned long long a,
                                     unsigned long long b) {
    asm("fma.rn.f32x2 %0, %1, %2, %0;" : "+l"(d) : "l"(a), "l"(b));
}
__device__ __forceinline__ unsigned long long pack2(float lo, float hi) {
    unsigned long long r;
    asm("mov.b64 %0, {%1, %2};" : "=l"(r) : "f"(lo), "f"(hi));
    return r;
}
__device__ __forceinline__ float2 unpack2(unsigned long long v) {
    float2 r;
    asm("mov.b64 {%0, %1}, %2;" : "=f"(r.x), "=f"(r.y) : "l"(v));
    return r;
}

// ---------------- kernel 0: prep = phiv (blocks 0..127) + lb (128..255) -----
__global__ void prep_kernel(const float* __restrict__ dec,
                            const float* __restrict__ Wphi,
                            const float* __restrict__ bphi,
                            const float* __restrict__ Wpsi,
                            const float* __restrict__ ck,
                            const float* __restrict__ Wloc,
                            const float* __restrict__ prev)
{
    __shared__ float sm[1184];
    int bx = blockIdx.x;
    int tid = threadIdx.x;   // 256

    if (bx < 128) {
        // ---- phiv for bh = bx ----
        float* dec_sm   = sm;            // 512
        float* phi_part = sm + 512;      // 2*128
        float* phi_sm   = sm + 768;      // 128
        int b = bx >> 2, h = bx & 3;

        for (int i = tid; i < D_; i += 256) dec_sm[i] = dec[(size_t)b * D_ + i];
        __syncthreads();

        {
            int k = tid & 127, sl = tid >> 7;
            const float* w = Wphi + (size_t)h * D_ * HD_ + (size_t)sl * 256 * HD_ + k;
            const float* ds = dec_sm + sl * 256;
            float a0 = 0.f, a1 = 0.f, a2 = 0.f, a3 = 0.f;
            #pragma unroll 8
            for (int d = 0; d < 256; d += 4) {
                a0 += ds[d + 0] * w[(size_t)(d + 0) * HD_];
                a1 += ds[d + 1] * w[(size_t)(d + 1) * HD_];
                a2 += ds[d + 2] * w[(size_t)(d + 2) * HD_];
                a3 += ds[d + 3] * w[(size_t)(d + 3) * HD_];
            }
            phi_part[sl * 128 + k] = (a0 + a1) + (a2 + a3);
        }
        __syncthreads();
        if (tid < HD_)
            phi_sm[tid] = phi_part[tid] + phi_part[128 + tid] + bphi[h * HD_ + tid];
        __syncthreads();

        for (int e = tid; e < D_; e += 256) {
            const float4* wp = reinterpret_cast<const float4*>(
                Wpsi + ((size_t)h * D_ + e) * HD_);
            float vv = 0.f;
            #pragma unroll 8
            for (int k4 = 0; k4 < HD_ / 4; k4++) {
                float4 ww = wp[k4];
                vv += ww.x * phi_sm[4 * k4 + 0] + ww.y * phi_sm[4 * k4 + 1]
                    + ww.z * phi_sm[4 * k4 + 2] + ww.w * phi_sm[4 * k4 + 3];
            }
            g_V[(size_t)bx * D_ + e] = vv;
        }
    } else {
        // ---- lb for (z, b) ----
        float* prevs = sm;               // 1024 + 30
        float* keffs = sm + 1056;        // 124
        int idx = bx - 128;
        int z = idx & 3, b = idx >> 2;
        int ubase = z * 1024;

        if (tid < CK_ * H_) {            // keff inline (cheap, redundant per block)
            int k = tid >> 2, h = tid & 3;
            float s = 0.f;
            #pragma unroll
            for (int f = 0; f < CF_; f++)
                s += ck[k * CF_ + f] * Wloc[f * H_ + h];
            keffs[tid] = s;
        }
        for (int i = tid; i < 1024 + CK_ - 1; i += 256) {
            int gu = ubase + i - 15;
            prevs[i] = (gu >= 0 && gu < U_) ? prev[(size_t)b * U_ + gu] : 0.f;
        }
        __syncthreads();

        float4* outp = reinterpret_cast<float4*>(
            g_LB + ((size_t)b * U_ + ubase) * H_);
        #pragma unroll
        for (int q = 0; q < 4; q++) {
            int ul = tid + 256 * q;
            float l0 = 0.f, l1 = 0.f, l2 = 0.f, l3 = 0.f;
            #pragma unroll
            for (int k = 0; k < CK_; k++) {
                float pv = prevs[ul + k];
                l0 += pv * keffs[k * H_ + 0];
                l1 += pv * keffs[k * H_ + 1];
                l2 += pv * keffs[k * H_ + 2];
                l3 += pv * keffs[k * H_ + 3];
            }
            outp[ul] = make_float4(l0, l1, l2, l3);
        }
    }
}

// ---------------- kernel 1: fused energy+exp+context ------------------------
// grid (NC, B), 256 threads, 4 CTAs/SM target (44 KB smem, <=64 regs).
// warp: h = warp&3, rg = warp>>2; rows rg*4..rg*4+3 per 8-row subtile.
// dynamic smem floats:
//   [0)      tiles  : 2*ST*D = 8192
//   [8192)   ctxred : H*D    = 2048   (two-phase rowgroup reduce)
//   [10240)  pall   : UC*H   = 512
//   [10752)  lbs    : UC*H   = 512
#define SMEM_F_FLOATS 11264
#define SMEM_F_BYTES (SMEM_F_FLOATS * 4)

__global__ void __launch_bounds__(256, 4)
fused_kernel(const float* __restrict__ enc)
{
    extern __shared__ float smem[];
    float* tiles  = smem;
    float* ctxred = smem + 8192;
    float* pall   = smem + 10240;
    float* lbs    = smem + 10752;

    int tid  = threadIdx.x;
    int warp = tid >> 5, lane = tid & 31;
    int h = warp & 3, rg = warp >> 2;
    int b  = blockIdx.y;
    int u0 = blockIdx.x * UC;

    const float* enc_base = enc + ((size_t)b * U_ + u0) * D_;
    uint32_t tiles_s = smem_u32(tiles);

    // prologue: stage subtiles 0, 1
    #pragma unroll
    for (int s = 0; s < 2; s++) {
        uint32_t dst = tiles_s + s * (ST * D_ * 4);
        const float* src = enc_base + s * ST * D_;
        #pragma unroll
        for (int q = 0; q < 4; q++) {
            int idx = tid + 256 * q;
            cp_async16(dst + idx * 16, src + idx * 4);
        }
        cp_commit();
    }

    // stage lb for the chunk
    #pragma unroll
    for (int q = 0; q < 2; q++) {
        int idx = tid + 256 * q;
        lbs[idx] = g_LB[((size_t)b * U_ + u0) * H_ + idx];
    }

    // v for this warp's head, packed pairs
    ulonglong2 v2[4];
    {
        const ulonglong2* vp = reinterpret_cast<const ulonglong2*>(
            g_V + (size_t)(b * H_ + h) * D_);
        #pragma unroll
        for (int i = 0; i < 4; i++) v2[i] = vp[lane + 32 * i];
    }

    unsigned long long ctx2[8];
    #pragma unroll
    for (int i = 0; i < 8; i++) ctx2[i] = 0ull;

    for (int s = 0; s < NSUB; s++) {
        if (s < NSUB - 1) cp_wait<1>(); else cp_wait<0>();
        __syncthreads();
        const float* tile = tiles + (s & 1) * (ST * D_);

        #pragma unroll
        for (int t = 0; t < 4; t++) {
            int r = rg * 4 + t;
            int uu = s * ST + r;
            const ulonglong2* row =
                reinterpret_cast<const ulonglong2*>(tile + r * D_);
            ulonglong2 X[4];
            #pragma unroll
            for (int i = 0; i < 4; i++) X[i] = row[lane + 32 * i];

            unsigned long long a2 = 0ull;
            #pragma unroll
            for (int i = 0; i < 4; i++) {
                fma2(a2, X[i].x, v2[i].x);
                fma2(a2, X[i].y, v2[i].y);
            }
            float2 f = unpack2(a2);
            float a = f.x + f.y;
            #pragma unroll
            for (int off = 16; off; off >>= 1)
                a += __shfl_xor_sync(0xffffffffu, a, off);
            float p = __expf(a + lbs[uu * H_ + h]);
            if (lane == 0) pall[uu * H_ + h] = p;
            unsigned long long pp = pack2(p, p);
            #pragma unroll
            for (int i = 0; i < 4; i++) {
                fma2(ctx2[2 * i + 0], X[i].x, pp);
                fma2(ctx2[2 * i + 1], X[i].y, pp);
            }
        }
        __syncthreads();   // done reading this buffer

        if (s + 2 < NSUB) {
            uint32_t dst = tiles_s + (s & 1) * (ST * D_ * 4);
            const float* src = enc_base + (s + 2) * ST * D_;
            #pragma unroll
            for (int q = 0; q < 4; q++) {
                int idx = tid + 256 * q;
                cp_async16(dst + idx * 16, src + idx * 4);
            }
            cp_commit();
        }
    }

    // two-phase rowgroup reduce into ctxred[h][e]
    float4 c[4];
    #pragma unroll
    for (int i = 0; i < 4; i++) {
        float2 lo = unpack2(ctx2[2 * i + 0]);
        float2 hi = unpack2(ctx2[2 * i + 1]);
        c[i] = make_float4(lo.x, lo.y, hi.x, hi.y);
    }
    float4* cr = reinterpret_cast<float4*>(ctxred + h * D_);
    if (rg == 0) {
        #pragma unroll
        for (int i = 0; i < 4; i++) cr[lane + 32 * i] = c[i];
    }
    __syncthreads();
    if (rg == 1) {
        #pragma unroll
        for (int i = 0; i < 4; i++) {
            float4 o = cr[lane + 32 * i];
            o.x += c[i].x; o.y += c[i].y; o.z += c[i].z; o.w += c[i].w;
            cr[lane + 32 * i] = o;
        }
    }
    __syncthreads();

    size_t chunk = (size_t)b * NC + blockIdx.x;

    #pragma unroll
    for (int q = 0; q < 8; q++) {
        int idx = tid + 256 * q;          // [0,2048) == [h][e]
        g_CTXP[chunk * (H_ * D_) + idx] = ctxred[idx];
    }

    // per-chunk sum of p
    if (warp < H_) {
        float sp = pall[lane * H_ + warp] + pall[(lane + 32) * H_ + warp]
                 + pall[(lane + 64) * H_ + warp] + pall[(lane + 96) * H_ + warp];
        #pragma unroll
        for (int off = 16; off; off >>= 1)
            sp += __shfl_xor_sync(0xffffffffu, sp, off);
        if (lane == 0) g_SP[chunk * H_ + warp] = sp;
    }

    // raw p -> g_P
    #pragma unroll
    for (int jj = 0; jj < 2; jj++) {
        int idx = tid + 256 * jj;
        g_P[((size_t)b * U_ + u0) * H_ + idx] = pall[idx];
    }
}

// ---------------- kernel 2: norm = combine (0..127) + aw (128..191) ---------
__global__ void norm_kernel(float* __restrict__ out)
{
    int bx = blockIdx.x;
    int tid = threadIdx.x;   // 512
    int warp = tid >> 5, lane = tid & 31;

    if (bx < 128) {
        int h = bx & 3, b = bx >> 2;
        __shared__ float S_sm;
        if (tid < 32) {
            float sc = g_SP[((size_t)b * NC + lane) * H_ + h];
            #pragma unroll
            for (int off = 16; off; off >>= 1)
                sc += __shfl_xor_sync(0xffffffffu, sc, off);
            if (lane == 0) S_sm = sc;
        }
        __syncthreads();
        float invS = 1.f / S_sm;

        const float* base = g_CTXP + (size_t)b * NC * H_ * D_ + h * D_ + tid;
        float a = 0.f;
        #pragma unroll 8
        for (int c = 0; c < NC; c++)
            a += base[(size_t)c * H_ * D_];
        g_CTX[(size_t)(b * H_ + h) * D_ + tid] = a * invS;
    } else {
        int q = bx - 128;        // 0..63
        int b = q >> 1, half = q & 1;
        __shared__ float S4[4];
        if (warp < 4) {
            float sc = g_SP[((size_t)b * NC + lane) * H_ + warp];
            #pragma unroll
            for (int off = 16; off; off >>= 1)
                sc += __shfl_xor_sync(0xffffffffu, sc, off);
            if (lane == 0) S4[warp] = 0.25f / sc;
        }
        __syncthreads();
        float i0 = S4[0], i1 = S4[1], i2 = S4[2], i3 = S4[3];

        const float4* p = reinterpret_cast<const float4*>(
            g_P + ((size_t)b * U_ + half * 2048) * H_);
        float* o = out + (size_t)B_ * AU_ + (size_t)b * U_ + half * 2048;
        #pragma unroll
        for (int k = 0; k < 4; k++) {
            int u = tid + 512 * k;
            float4 v = p[u];
            o[u] = v.x * i0 + v.y * i1 + v.z * i2 + v.w * i3;
        }
    }
}

// ---------------- kernel 3 (PROFILED): out GEMM partials --------------------
__global__ void outp_kernel(const float* __restrict__ Wout)
{
    extern __shared__ float c_sm[];   // [b][i] : 32 x 512
    int cg = blockIdx.x, s = blockIdx.y;
    int tid = threadIdx.x;
    int col = cg * 32 + (tid & 31);
    int bg  = tid >> 5;

    for (int k = tid; k < 32 * 512; k += 256) {
        int bb = k >> 9, i = k & 511;
        c_sm[k] = g_CTX[(size_t)bb * (H_ * D_) + s * 512 + i];
    }
    __syncthreads();

    float acc0 = 0.f, acc1 = 0.f, acc2 = 0.f, acc3 = 0.f;
    const float* wp = Wout + (size_t)s * 512 * AU_ + col;
    const float* c0 = c_sm + (4 * bg + 0) * 512;
    const float* c1 = c_sm + (4 * bg + 1) * 512;
    const float* c2 = c_sm + (4 * bg + 2) * 512;
    const float* c3 = c_sm + (4 * bg + 3) * 512;
    #pragma unroll 8
    for (int i = 0; i < 512; i++) {
        float w = wp[(size_t)i * AU_];
        acc0 += c0[i] * w;
        acc1 += c1[i] * w;
        acc2 += c2[i] * w;
        acc3 += c3[i] * w;
    }
    float* op = g_OUTP + (size_t)s * B_ * AU_ + col;
    op[(4 * bg + 0) * AU_] = acc0;
    op[(4 * bg + 1) * AU_] = acc1;
    op[(4 * bg + 2) * AU_] = acc2;
    op[(4 * bg + 3) * AU_] = acc3;
}

// ---------------- kernel 4: out final ----------------------------------------
__global__ void outf_kernel(const float* __restrict__ bout,
                            float* __restrict__ out)
{
    int b = blockIdx.x, t = threadIdx.x;
    float v = bout[t]
            + g_OUTP[(0 * B_ + b) * AU_ + t] + g_OUTP[(1 * B_ + b) * AU_ + t]
            + g_OUTP[(2 * B_ + b) * AU_ + t] + g_OUTP[(3 * B_ + b) * AU_ + t];
    out[(size_t)b * AU_ + t] = v;
}

// ---------------------------------------------------------------------------
extern "C" void kernel_launch(void* const* d_in, const int* in_sizes, int n_in,
                              void* d_out, int out_size)
{
    const float* dec   = (const float*)d_in[0];
    const float* enc   = (const float*)d_in[1];
    const float* prev  = (const float*)d_in[2];
    const float* Wphi  = (const float*)d_in[3];
    const float* bphi  = (const float*)d_in[4];
    const float* Wpsi  = (const float*)d_in[5];
    // d_in[6] = bpsi: constant along u per (b,h) -> softmax-invariant, unused
    const float* ck    = (const float*)d_in[7];
    const float* Wloc  = (const float*)d_in[8];
    const float* Wout  = (const float*)d_in[9];
    const float* bout  = (const float*)d_in[10];
    float* out = (float*)d_out;

    cudaFuncSetAttribute(outp_kernel,
                         cudaFuncAttributeMaxDynamicSharedMemorySize,
                         32 * 512 * 4);

    prep_kernel<<<256, 256>>>(dec, Wphi, bphi, Wpsi, ck, Wloc, prev); // idx 0
    fused_kernel<<<dim3(NC, B_), 256, SMEM_F_BYTES>>>(enc);           // idx 1
    norm_kernel<<<192, 512>>>(out);                                   // idx 2
    outp_kernel<<<dim3(16, 4), 256, 32 * 512 * 4>>>(Wout);            // idx 3 <- profiled
    outf_kernel<<<B_, 512>>>(bout, out);                              // idx 4
}

// round 9
// speedup vs baseline: 2.3488x; 1.4949x over previous
#include <cuda_runtime.h>
#include <cuda_bf16.h>
#include <cstdint>

// Problem constants
#define B_    32
#define U_    4096
#define D_    512
#define H_    4
#define HD_   128
#define CK_   31
#define CF_   32
#define AU_   512

#define UC    128            // u rows per CTA chunk
#define NC    (U_ / UC)      // 32 chunks per batch
#define ST    8              // rows per pipeline stage
#define NSUB  (UC / ST)      // 16
#define KS_   16             // k-slices for the out GEMM

// ---------------- scratch (device globals) ----------------------------------
__device__ float g_V[B_ * H_ * D_];
__device__ float g_LB[(size_t)B_ * U_ * H_];                // location bias [b][u][h]
__device__ float g_P[(size_t)B_ * U_ * H_];                 // exp(energy), [b][u][h]
__device__ float g_CTXP[(size_t)B_ * NC * H_ * D_];         // per-chunk ctx partials
__device__ float g_SP[B_ * NC * H_];                        // per-chunk sum of p
__device__ float g_CTX[B_ * H_ * D_];                       // normalized context
__device__ float g_OUTP[KS_ * B_ * AU_];                    // out GEMM partials

// ---------------- PTX helpers -----------------------------------------------
__device__ __forceinline__ uint32_t smem_u32(const void* p) {
    uint32_t a;
    asm("{ .reg .u64 t; cvta.to.shared.u64 t, %1; cvt.u32.u64 %0, t; }"
        : "=r"(a) : "l"(p));
    return a;
}
__device__ __forceinline__ void cp_async16(uint32_t dst, const void* src) {
    asm volatile("cp.async.cg.shared.global [%0], [%1], 16;"
                 :: "r"(dst), "l"(src) : "memory");
}
__device__ __forceinline__ void cp_commit() {
    asm volatile("cp.async.commit_group;" ::: "memory");
}
template <int N>
__device__ __forceinline__ void cp_wait() {
    asm volatile("cp.async.wait_group %0;" :: "n"(N) : "memory");
}
__device__ __forceinline__ void fma2(unsigned long long& d,
                                     unsigned long long a,
                                     unsigned long long b) {
    asm("fma.rn.f32x2 %0, %1, %2, %0;" : "+l"(d) : "l"(a), "l"(b));
}
__device__ __forceinline__ unsigned long long pack2(float lo, float hi) {
    unsigned long long r;
    asm("mov.b64 %0, {%1, %2};" : "=l"(r) : "f"(lo), "f"(hi));
    return r;
}
__device__ __forceinline__ float2 unpack2(unsigned long long v) {
    float2 r;
    asm("mov.b64 {%0, %1}, %2;" : "=f"(r.x), "=f"(r.y) : "l"(v));
    return r;
}

// ---------------- kernel 0: prep = phiv (blocks 0..127) + lb (128..255) -----
__global__ void prep_kernel(const float* __restrict__ dec,
                            const float* __restrict__ Wphi,
                            const float* __restrict__ bphi,
                            const float* __restrict__ Wpsi,
                            const float* __restrict__ ck,
                            const float* __restrict__ Wloc,
                            const float* __restrict__ prev)
{
    __shared__ float sm[1184];
    int bx = blockIdx.x;
    int tid = threadIdx.x;   // 256

    if (bx < 128) {
        // ---- phiv for bh = bx ----
        float* dec_sm   = sm;            // 512
        float* phi_part = sm + 512;      // 2*128
        float* phi_sm   = sm + 768;      // 128
        int b = bx >> 2, h = bx & 3;

        for (int i = tid; i < D_; i += 256) dec_sm[i] = dec[(size_t)b * D_ + i];
        __syncthreads();

        {
            int k = tid & 127, sl = tid >> 7;
            const float* w = Wphi + (size_t)h * D_ * HD_ + (size_t)sl * 256 * HD_ + k;
            const float* ds = dec_sm + sl * 256;
            float a0 = 0.f, a1 = 0.f, a2 = 0.f, a3 = 0.f;
            #pragma unroll 8
            for (int d = 0; d < 256; d += 4) {
                a0 += ds[d + 0] * w[(size_t)(d + 0) * HD_];
                a1 += ds[d + 1] * w[(size_t)(d + 1) * HD_];
                a2 += ds[d + 2] * w[(size_t)(d + 2) * HD_];
                a3 += ds[d + 3] * w[(size_t)(d + 3) * HD_];
            }
            phi_part[sl * 128 + k] = (a0 + a1) + (a2 + a3);
        }
        __syncthreads();
        if (tid < HD_)
            phi_sm[tid] = phi_part[tid] + phi_part[128 + tid] + bphi[h * HD_ + tid];
        __syncthreads();

        for (int e = tid; e < D_; e += 256) {
            const float4* wp = reinterpret_cast<const float4*>(
                Wpsi + ((size_t)h * D_ + e) * HD_);
            float vv = 0.f;
            #pragma unroll 8
            for (int k4 = 0; k4 < HD_ / 4; k4++) {
                float4 ww = wp[k4];
                vv += ww.x * phi_sm[4 * k4 + 0] + ww.y * phi_sm[4 * k4 + 1]
                    + ww.z * phi_sm[4 * k4 + 2] + ww.w * phi_sm[4 * k4 + 3];
            }
            g_V[(size_t)bx * D_ + e] = vv;
        }
    } else {
        // ---- lb for (z, b) ----
        float* prevs = sm;               // 1024 + 30
        float* keffs = sm + 1056;        // 124
        int idx = bx - 128;
        int z = idx & 3, b = idx >> 2;
        int ubase = z * 1024;

        if (tid < CK_ * H_) {
            int k = tid >> 2, h = tid & 3;
            float s = 0.f;
            #pragma unroll
            for (int f = 0; f < CF_; f++)
                s += ck[k * CF_ + f] * Wloc[f * H_ + h];
            keffs[tid] = s;
        }
        for (int i = tid; i < 1024 + CK_ - 1; i += 256) {
            int gu = ubase + i - 15;
            prevs[i] = (gu >= 0 && gu < U_) ? prev[(size_t)b * U_ + gu] : 0.f;
        }
        __syncthreads();

        float4* outp = reinterpret_cast<float4*>(
            g_LB + ((size_t)b * U_ + ubase) * H_);
        #pragma unroll
        for (int q = 0; q < 4; q++) {
            int ul = tid + 256 * q;
            float l0 = 0.f, l1 = 0.f, l2 = 0.f, l3 = 0.f;
            #pragma unroll
            for (int k = 0; k < CK_; k++) {
                float pv = prevs[ul + k];
                l0 += pv * keffs[k * H_ + 0];
                l1 += pv * keffs[k * H_ + 1];
                l2 += pv * keffs[k * H_ + 2];
                l3 += pv * keffs[k * H_ + 3];
            }
            outp[ul] = make_float4(l0, l1, l2, l3);
        }
    }
}

// ---------------- kernel 1: fused energy+exp+context ------------------------
// dynamic smem floats:
//   [0)      tiles  : 2*ST*D = 8192
//   [8192)   ctxred : H*D    = 2048
//   [10240)  pall   : UC*H   = 512
//   [10752)  lbs    : UC*H   = 512
#define SMEM_F_FLOATS 11264
#define SMEM_F_BYTES (SMEM_F_FLOATS * 4)

__global__ void __launch_bounds__(256, 4)
fused_kernel(const float* __restrict__ enc)
{
    extern __shared__ float smem[];
    float* tiles  = smem;
    float* ctxred = smem + 8192;
    float* pall   = smem + 10240;
    float* lbs    = smem + 10752;

    int tid  = threadIdx.x;
    int warp = tid >> 5, lane = tid & 31;
    int h = warp & 3, rg = warp >> 2;
    int b  = blockIdx.y;
    int u0 = blockIdx.x * UC;

    const float* enc_base = enc + ((size_t)b * U_ + u0) * D_;
    uint32_t tiles_s = smem_u32(tiles);

    #pragma unroll
    for (int s = 0; s < 2; s++) {
        uint32_t dst = tiles_s + s * (ST * D_ * 4);
        const float* src = enc_base + s * ST * D_;
        #pragma unroll
        for (int q = 0; q < 4; q++) {
            int idx = tid + 256 * q;
            cp_async16(dst + idx * 16, src + idx * 4);
        }
        cp_commit();
    }

    #pragma unroll
    for (int q = 0; q < 2; q++) {
        int idx = tid + 256 * q;
        lbs[idx] = g_LB[((size_t)b * U_ + u0) * H_ + idx];
    }

    ulonglong2 v2[4];
    {
        const ulonglong2* vp = reinterpret_cast<const ulonglong2*>(
            g_V + (size_t)(b * H_ + h) * D_);
        #pragma unroll
        for (int i = 0; i < 4; i++) v2[i] = vp[lane + 32 * i];
    }

    unsigned long long ctx2[8];
    #pragma unroll
    for (int i = 0; i < 8; i++) ctx2[i] = 0ull;

    for (int s = 0; s < NSUB; s++) {
        if (s < NSUB - 1) cp_wait<1>(); else cp_wait<0>();
        __syncthreads();
        const float* tile = tiles + (s & 1) * (ST * D_);

        #pragma unroll
        for (int t = 0; t < 4; t++) {
            int r = rg * 4 + t;
            int uu = s * ST + r;
            const ulonglong2* row =
                reinterpret_cast<const ulonglong2*>(tile + r * D_);
            ulonglong2 X[4];
            #pragma unroll
            for (int i = 0; i < 4; i++) X[i] = row[lane + 32 * i];

            unsigned long long a2 = 0ull;
            #pragma unroll
            for (int i = 0; i < 4; i++) {
                fma2(a2, X[i].x, v2[i].x);
                fma2(a2, X[i].y, v2[i].y);
            }
            float2 f = unpack2(a2);
            float a = f.x + f.y;
            #pragma unroll
            for (int off = 16; off; off >>= 1)
                a += __shfl_xor_sync(0xffffffffu, a, off);
            float p = __expf(a + lbs[uu * H_ + h]);
            if (lane == 0) pall[uu * H_ + h] = p;
            unsigned long long pp = pack2(p, p);
            #pragma unroll
            for (int i = 0; i < 4; i++) {
                fma2(ctx2[2 * i + 0], X[i].x, pp);
                fma2(ctx2[2 * i + 1], X[i].y, pp);
            }
        }
        __syncthreads();

        if (s + 2 < NSUB) {
            uint32_t dst = tiles_s + (s & 1) * (ST * D_ * 4);
            const float* src = enc_base + (s + 2) * ST * D_;
            #pragma unroll
            for (int q = 0; q < 4; q++) {
                int idx = tid + 256 * q;
                cp_async16(dst + idx * 16, src + idx * 4);
            }
            cp_commit();
        }
    }

    float4 c[4];
    #pragma unroll
    for (int i = 0; i < 4; i++) {
        float2 lo = unpack2(ctx2[2 * i + 0]);
        float2 hi = unpack2(ctx2[2 * i + 1]);
        c[i] = make_float4(lo.x, lo.y, hi.x, hi.y);
    }
    float4* cr = reinterpret_cast<float4*>(ctxred + h * D_);
    if (rg == 0) {
        #pragma unroll
        for (int i = 0; i < 4; i++) cr[lane + 32 * i] = c[i];
    }
    __syncthreads();
    if (rg == 1) {
        #pragma unroll
        for (int i = 0; i < 4; i++) {
            float4 o = cr[lane + 32 * i];
            o.x += c[i].x; o.y += c[i].y; o.z += c[i].z; o.w += c[i].w;
            cr[lane + 32 * i] = o;
        }
    }
    __syncthreads();

    size_t chunk = (size_t)b * NC + blockIdx.x;

    #pragma unroll
    for (int q = 0; q < 8; q++) {
        int idx = tid + 256 * q;
        g_CTXP[chunk * (H_ * D_) + idx] = ctxred[idx];
    }

    if (warp < H_) {
        float sp = pall[lane * H_ + warp] + pall[(lane + 32) * H_ + warp]
                 + pall[(lane + 64) * H_ + warp] + pall[(lane + 96) * H_ + warp];
        #pragma unroll
        for (int off = 16; off; off >>= 1)
            sp += __shfl_xor_sync(0xffffffffu, sp, off);
        if (lane == 0) g_SP[chunk * H_ + warp] = sp;
    }

    #pragma unroll
    for (int jj = 0; jj < 2; jj++) {
        int idx = tid + 256 * jj;
        g_P[((size_t)b * U_ + u0) * H_ + idx] = pall[idx];
    }
}

// ---------------- kernel 2: norm = combine (0..127) + aw (128..191) ---------
__global__ void norm_kernel(float* __restrict__ out)
{
    int bx = blockIdx.x;
    int tid = threadIdx.x;   // 512
    int warp = tid >> 5, lane = tid & 31;

    if (bx < 128) {
        int h = bx & 3, b = bx >> 2;
        __shared__ float S_sm;
        if (tid < 32) {
            float sc = g_SP[((size_t)b * NC + lane) * H_ + h];
            #pragma unroll
            for (int off = 16; off; off >>= 1)
                sc += __shfl_xor_sync(0xffffffffu, sc, off);
            if (lane == 0) S_sm = sc;
        }
        __syncthreads();
        float invS = 1.f / S_sm;

        const float* base = g_CTXP + (size_t)b * NC * H_ * D_ + h * D_ + tid;
        float a = 0.f;
        #pragma unroll 8
        for (int c = 0; c < NC; c++)
            a += base[(size_t)c * H_ * D_];
        g_CTX[(size_t)(b * H_ + h) * D_ + tid] = a * invS;
    } else {
        int q = bx - 128;        // 0..63
        int b = q >> 1, half = q & 1;
        __shared__ float S4[4];
        if (warp < 4) {
            float sc = g_SP[((size_t)b * NC + lane) * H_ + warp];
            #pragma unroll
            for (int off = 16; off; off >>= 1)
                sc += __shfl_xor_sync(0xffffffffu, sc, off);
            if (lane == 0) S4[warp] = 0.25f / sc;
        }
        __syncthreads();
        float i0 = S4[0], i1 = S4[1], i2 = S4[2], i3 = S4[3];

        const float4* p = reinterpret_cast<const float4*>(
            g_P + ((size_t)b * U_ + half * 2048) * H_);
        float* o = out + (size_t)B_ * AU_ + (size_t)b * U_ + half * 2048;
        #pragma unroll
        for (int k = 0; k < 4; k++) {
            int u = tid + 512 * k;
            float4 v = p[u];
            o[u] = v.x * i0 + v.y * i1 + v.z * i2 + v.w * i3;
        }
    }
}

// ---------------- kernel 3 (PROFILED): out GEMM partials --------------------
// grid (16 colgroups, 16 k-slices), block 256 = 32 cols x 8 bgroups (4 b each).
// Each block: k range ks*128..+128, cols cg*32..+32. smem: ctx slice 32x128.
__global__ void outp_kernel(const float* __restrict__ Wout)
{
    __shared__ float c_sm[32 * 128];  // [b][kl] : 16 KB
    int cg = blockIdx.x, ks = blockIdx.y;
    int tid = threadIdx.x;
    int col = cg * 32 + (tid & 31);
    int bg  = tid >> 5;

    // load ctx slice: c_sm[b][kl] = g_CTX[b*2048 + ks*128 + kl]
    for (int k = tid; k < 32 * 128; k += 256) {
        int bb = k >> 7, kl = k & 127;
        c_sm[k] = g_CTX[(size_t)bb * (H_ * D_) + ks * 128 + kl];
    }
    __syncthreads();

    float acc0 = 0.f, acc1 = 0.f, acc2 = 0.f, acc3 = 0.f;
    const float* wp = Wout + ((size_t)ks * 128) * AU_ + col;
    const float* c0 = c_sm + (4 * bg + 0) * 128;
    const float* c1 = c_sm + (4 * bg + 1) * 128;
    const float* c2 = c_sm + (4 * bg + 2) * 128;
    const float* c3 = c_sm + (4 * bg + 3) * 128;
    #pragma unroll 8
    for (int i = 0; i < 128; i++) {
        float w = wp[(size_t)i * AU_];
        acc0 += c0[i] * w;
        acc1 += c1[i] * w;
        acc2 += c2[i] * w;
        acc3 += c3[i] * w;
    }
    float* op = g_OUTP + (size_t)ks * B_ * AU_ + col;
    op[(4 * bg + 0) * AU_] = acc0;
    op[(4 * bg + 1) * AU_] = acc1;
    op[(4 * bg + 2) * AU_] = acc2;
    op[(4 * bg + 3) * AU_] = acc3;
}

// ---------------- kernel 4: out final ----------------------------------------
__global__ void outf_kernel(const float* __restrict__ bout,
                            float* __restrict__ out)
{
    int b = blockIdx.x, t = threadIdx.x;   // 32 x 512
    float v = bout[t];
    #pragma unroll
    for (int s = 0; s < KS_; s++)
        v += g_OUTP[((size_t)s * B_ + b) * AU_ + t];
    out[(size_t)b * AU_ + t] = v;
}

// ---------------------------------------------------------------------------
extern "C" void kernel_launch(void* const* d_in, const int* in_sizes, int n_in,
                              void* d_out, int out_size)
{
    const float* dec   = (const float*)d_in[0];
    const float* enc   = (const float*)d_in[1];
    const float* prev  = (const float*)d_in[2];
    const float* Wphi  = (const float*)d_in[3];
    const float* bphi  = (const float*)d_in[4];
    const float* Wpsi  = (const float*)d_in[5];
    // d_in[6] = bpsi: constant along u per (b,h) -> softmax-invariant, unused
    const float* ck    = (const float*)d_in[7];
    const float* Wloc  = (const float*)d_in[8];
    const float* Wout  = (const float*)d_in[9];
    const float* bout  = (const float*)d_in[10];
    float* out = (float*)d_out;

    prep_kernel<<<256, 256>>>(dec, Wphi, bphi, Wpsi, ck, Wloc, prev); // idx 0
    fused_kernel<<<dim3(NC, B_), 256, SMEM_F_BYTES>>>(enc);           // idx 1
    norm_kernel<<<192, 512>>>(out);                                   // idx 2
    outp_kernel<<<dim3(16, KS_), 256>>>(Wout);                        // idx 3 <- profiled
    outf_kernel<<<B_, 512>>>(bout, out);                              // idx 4
}

// round 10
// speedup vs baseline: 2.5274x; 1.0761x over previous
#include <cuda_runtime.h>
#include <cuda_bf16.h>
#include <cstdint>

// Problem constants
#define B_    32
#define U_    4096
#define D_    512
#define H_    4
#define HD_   128
#define CK_   31
#define CF_   32
#define AU_   512

#define UC    128            // u rows per CTA chunk
#define NC    (U_ / UC)      // 32 chunks per batch
#define ST    8              // rows per pipeline stage
#define NSUB  (UC / ST)      // 16
#define KS_   32             // k-slices for the out GEMM (depth 64 each)

// ---------------- scratch (device globals) ----------------------------------
__device__ float g_V[B_ * H_ * D_];
__device__ float g_LB[(size_t)B_ * U_ * H_];                // location bias [b][u][h]
__device__ float g_P[(size_t)B_ * U_ * H_];                 // exp(energy), [b][u][h]
__device__ float g_CTXP[(size_t)B_ * NC * H_ * D_];         // per-chunk ctx partials
__device__ float g_SP[B_ * NC * H_];                        // per-chunk sum of p
__device__ float g_CTX[B_ * H_ * D_];                       // normalized context
__device__ float g_OUTP[KS_ * B_ * AU_];                    // out GEMM partials

// ---------------- PTX helpers -----------------------------------------------
__device__ __forceinline__ uint32_t smem_u32(const void* p) {
    uint32_t a;
    asm("{ .reg .u64 t; cvta.to.shared.u64 t, %1; cvt.u32.u64 %0, t; }"
        : "=r"(a) : "l"(p));
    return a;
}
__device__ __forceinline__ void cp_async16(uint32_t dst, const void* src) {
    asm volatile("cp.async.cg.shared.global [%0], [%1], 16;"
                 :: "r"(dst), "l"(src) : "memory");
}
__device__ __forceinline__ void cp_commit() {
    asm volatile("cp.async.commit_group;" ::: "memory");
}
template <int N>
__device__ __forceinline__ void cp_wait() {
    asm volatile("cp.async.wait_group %0;" :: "n"(N) : "memory");
}
__device__ __forceinline__ void fma2(unsigned long long& d,
                                     unsigned long long a,
                                     unsigned long long b) {
    asm("fma.rn.f32x2 %0, %1, %2, %0;" : "+l"(d) : "l"(a), "l"(b));
}
__device__ __forceinline__ unsigned long long pack2(float lo, float hi) {
    unsigned long long r;
    asm("mov.b64 %0, {%1, %2};" : "=l"(r) : "f"(lo), "f"(hi));
    return r;
}
__device__ __forceinline__ float2 unpack2(unsigned long long v) {
    float2 r;
    asm("mov.b64 {%0, %1}, %2;" : "=f"(r.x), "=f"(r.y) : "l"(v));
    return r;
}

// ---------------- kernel 0: prep = phiv (blocks 0..127) + lb (128..255) -----
__global__ void prep_kernel(const float* __restrict__ dec,
                            const float* __restrict__ Wphi,
                            const float* __restrict__ bphi,
                            const float* __restrict__ Wpsi,
                            const float* __restrict__ ck,
                            const float* __restrict__ Wloc,
                            const float* __restrict__ prev)
{
    __shared__ float sm[1184];
    int bx = blockIdx.x;
    int tid = threadIdx.x;   // 256

    if (bx < 128) {
        float* dec_sm   = sm;            // 512
        float* phi_part = sm + 512;      // 2*128
        float* phi_sm   = sm + 768;      // 128
        int b = bx >> 2, h = bx & 3;

        for (int i = tid; i < D_; i += 256) dec_sm[i] = dec[(size_t)b * D_ + i];
        __syncthreads();

        {
            int k = tid & 127, sl = tid >> 7;
            const float* w = Wphi + (size_t)h * D_ * HD_ + (size_t)sl * 256 * HD_ + k;
            const float* ds = dec_sm + sl * 256;
            float a0 = 0.f, a1 = 0.f, a2 = 0.f, a3 = 0.f;
            #pragma unroll 8
            for (int d = 0; d < 256; d += 4) {
                a0 += ds[d + 0] * w[(size_t)(d + 0) * HD_];
                a1 += ds[d + 1] * w[(size_t)(d + 1) * HD_];
                a2 += ds[d + 2] * w[(size_t)(d + 2) * HD_];
                a3 += ds[d + 3] * w[(size_t)(d + 3) * HD_];
            }
            phi_part[sl * 128 + k] = (a0 + a1) + (a2 + a3);
        }
        __syncthreads();
        if (tid < HD_)
            phi_sm[tid] = phi_part[tid] + phi_part[128 + tid] + bphi[h * HD_ + tid];
        __syncthreads();

        for (int e = tid; e < D_; e += 256) {
            const float4* wp = reinterpret_cast<const float4*>(
                Wpsi + ((size_t)h * D_ + e) * HD_);
            float vv = 0.f;
            #pragma unroll 8
            for (int k4 = 0; k4 < HD_ / 4; k4++) {
                float4 ww = wp[k4];
                vv += ww.x * phi_sm[4 * k4 + 0] + ww.y * phi_sm[4 * k4 + 1]
                    + ww.z * phi_sm[4 * k4 + 2] + ww.w * phi_sm[4 * k4 + 3];
            }
            g_V[(size_t)bx * D_ + e] = vv;
        }
    } else {
        float* prevs = sm;               // 1024 + 30
        float* keffs = sm + 1056;        // 124
        int idx = bx - 128;
        int z = idx & 3, b = idx >> 2;
        int ubase = z * 1024;

        if (tid < CK_ * H_) {
            int k = tid >> 2, h = tid & 3;
            float s = 0.f;
            #pragma unroll
            for (int f = 0; f < CF_; f++)
                s += ck[k * CF_ + f] * Wloc[f * H_ + h];
            keffs[tid] = s;
        }
        for (int i = tid; i < 1024 + CK_ - 1; i += 256) {
            int gu = ubase + i - 15;
            prevs[i] = (gu >= 0 && gu < U_) ? prev[(size_t)b * U_ + gu] : 0.f;
        }
        __syncthreads();

        float4* outp = reinterpret_cast<float4*>(
            g_LB + ((size_t)b * U_ + ubase) * H_);
        #pragma unroll
        for (int q = 0; q < 4; q++) {
            int ul = tid + 256 * q;
            float l0 = 0.f, l1 = 0.f, l2 = 0.f, l3 = 0.f;
            #pragma unroll
            for (int k = 0; k < CK_; k++) {
                float pv = prevs[ul + k];
                l0 += pv * keffs[k * H_ + 0];
                l1 += pv * keffs[k * H_ + 1];
                l2 += pv * keffs[k * H_ + 2];
                l3 += pv * keffs[k * H_ + 3];
            }
            outp[ul] = make_float4(l0, l1, l2, l3);
        }
    }
}

// ---------------- kernel 1: fused energy+exp+context ------------------------
#define SMEM_F_FLOATS 11264
#define SMEM_F_BYTES (SMEM_F_FLOATS * 4)

__global__ void __launch_bounds__(256, 4)
fused_kernel(const float* __restrict__ enc)
{
    extern __shared__ float smem[];
    float* tiles  = smem;
    float* ctxred = smem + 8192;
    float* pall   = smem + 10240;
    float* lbs    = smem + 10752;

    int tid  = threadIdx.x;
    int warp = tid >> 5, lane = tid & 31;
    int h = warp & 3, rg = warp >> 2;
    int b  = blockIdx.y;
    int u0 = blockIdx.x * UC;

    const float* enc_base = enc + ((size_t)b * U_ + u0) * D_;
    uint32_t tiles_s = smem_u32(tiles);

    #pragma unroll
    for (int s = 0; s < 2; s++) {
        uint32_t dst = tiles_s + s * (ST * D_ * 4);
        const float* src = enc_base + s * ST * D_;
        #pragma unroll
        for (int q = 0; q < 4; q++) {
            int idx = tid + 256 * q;
            cp_async16(dst + idx * 16, src + idx * 4);
        }
        cp_commit();
    }

    #pragma unroll
    for (int q = 0; q < 2; q++) {
        int idx = tid + 256 * q;
        lbs[idx] = g_LB[((size_t)b * U_ + u0) * H_ + idx];
    }

    ulonglong2 v2[4];
    {
        const ulonglong2* vp = reinterpret_cast<const ulonglong2*>(
            g_V + (size_t)(b * H_ + h) * D_);
        #pragma unroll
        for (int i = 0; i < 4; i++) v2[i] = vp[lane + 32 * i];
    }

    unsigned long long ctx2[8];
    #pragma unroll
    for (int i = 0; i < 8; i++) ctx2[i] = 0ull;

    for (int s = 0; s < NSUB; s++) {
        if (s < NSUB - 1) cp_wait<1>(); else cp_wait<0>();
        __syncthreads();
        const float* tile = tiles + (s & 1) * (ST * D_);

        #pragma unroll
        for (int t = 0; t < 4; t++) {
            int r = rg * 4 + t;
            int uu = s * ST + r;
            const ulonglong2* row =
                reinterpret_cast<const ulonglong2*>(tile + r * D_);
            ulonglong2 X[4];
            #pragma unroll
            for (int i = 0; i < 4; i++) X[i] = row[lane + 32 * i];

            unsigned long long a2 = 0ull;
            #pragma unroll
            for (int i = 0; i < 4; i++) {
                fma2(a2, X[i].x, v2[i].x);
                fma2(a2, X[i].y, v2[i].y);
            }
            float2 f = unpack2(a2);
            float a = f.x + f.y;
            #pragma unroll
            for (int off = 16; off; off >>= 1)
                a += __shfl_xor_sync(0xffffffffu, a, off);
            float p = __expf(a + lbs[uu * H_ + h]);
            if (lane == 0) pall[uu * H_ + h] = p;
            unsigned long long pp = pack2(p, p);
            #pragma unroll
            for (int i = 0; i < 4; i++) {
                fma2(ctx2[2 * i + 0], X[i].x, pp);
                fma2(ctx2[2 * i + 1], X[i].y, pp);
            }
        }
        __syncthreads();

        if (s + 2 < NSUB) {
            uint32_t dst = tiles_s + (s & 1) * (ST * D_ * 4);
            const float* src = enc_base + (s + 2) * ST * D_;
            #pragma unroll
            for (int q = 0; q < 4; q++) {
                int idx = tid + 256 * q;
                cp_async16(dst + idx * 16, src + idx * 4);
            }
            cp_commit();
        }
    }

    float4 c[4];
    #pragma unroll
    for (int i = 0; i < 4; i++) {
        float2 lo = unpack2(ctx2[2 * i + 0]);
        float2 hi = unpack2(ctx2[2 * i + 1]);
        c[i] = make_float4(lo.x, lo.y, hi.x, hi.y);
    }
    float4* cr = reinterpret_cast<float4*>(ctxred + h * D_);
    if (rg == 0) {
        #pragma unroll
        for (int i = 0; i < 4; i++) cr[lane + 32 * i] = c[i];
    }
    __syncthreads();
    if (rg == 1) {
        #pragma unroll
        for (int i = 0; i < 4; i++) {
            float4 o = cr[lane + 32 * i];
            o.x += c[i].x; o.y += c[i].y; o.z += c[i].z; o.w += c[i].w;
            cr[lane + 32 * i] = o;
        }
    }
    __syncthreads();

    size_t chunk = (size_t)b * NC + blockIdx.x;

    #pragma unroll
    for (int q = 0; q < 8; q++) {
        int idx = tid + 256 * q;
        g_CTXP[chunk * (H_ * D_) + idx] = ctxred[idx];
    }

    if (warp < H_) {
        float sp = pall[lane * H_ + warp] + pall[(lane + 32) * H_ + warp]
                 + pall[(lane + 64) * H_ + warp] + pall[(lane + 96) * H_ + warp];
        #pragma unroll
        for (int off = 16; off; off >>= 1)
            sp += __shfl_xor_sync(0xffffffffu, sp, off);
        if (lane == 0) g_SP[chunk * H_ + warp] = sp;
    }

    #pragma unroll
    for (int jj = 0; jj < 2; jj++) {
        int idx = tid + 256 * jj;
        g_P[((size_t)b * U_ + u0) * H_ + idx] = pall[idx];
    }
}

// ---------------- kernel 2: norm = combine (0..127) + aw (128..191) ---------
__global__ void norm_kernel(float* __restrict__ out)
{
    int bx = blockIdx.x;
    int tid = threadIdx.x;   // 512
    int warp = tid >> 5, lane = tid & 31;

    if (bx < 128) {
        int h = bx & 3, b = bx >> 2;
        __shared__ float S_sm;
        if (tid < 32) {
            float sc = g_SP[((size_t)b * NC + lane) * H_ + h];
            #pragma unroll
            for (int off = 16; off; off >>= 1)
                sc += __shfl_xor_sync(0xffffffffu, sc, off);
            if (lane == 0) S_sm = sc;
        }
        __syncthreads();
        float invS = 1.f / S_sm;

        const float* base = g_CTXP + (size_t)b * NC * H_ * D_ + h * D_ + tid;
        float a = 0.f;
        #pragma unroll 8
        for (int c = 0; c < NC; c++)
            a += base[(size_t)c * H_ * D_];
        g_CTX[(size_t)(b * H_ + h) * D_ + tid] = a * invS;
    } else {
        int q = bx - 128;        // 0..63
        int b = q >> 1, half = q & 1;
        __shared__ float S4[4];
        if (warp < 4) {
            float sc = g_SP[((size_t)b * NC + lane) * H_ + warp];
            #pragma unroll
            for (int off = 16; off; off >>= 1)
                sc += __shfl_xor_sync(0xffffffffu, sc, off);
            if (lane == 0) S4[warp] = 0.25f / sc;
        }
        __syncthreads();
        float i0 = S4[0], i1 = S4[1], i2 = S4[2], i3 = S4[3];

        const float4* p = reinterpret_cast<const float4*>(
            g_P + ((size_t)b * U_ + half * 2048) * H_);
        float* o = out + (size_t)B_ * AU_ + (size_t)b * U_ + half * 2048;
        #pragma unroll
        for (int k = 0; k < 4; k++) {
            int u = tid + 512 * k;
            float4 v = p[u];
            o[u] = v.x * i0 + v.y * i1 + v.z * i2 + v.w * i3;
        }
    }
}

// ---------------- kernel 3 (PROFILED): out GEMM partials --------------------
// grid (4 colgroups of 128, KS_=32 k-slices of 64), block 256 = 32 lanes x 8 bg.
// Lane owns 4 consecutive cols (float4 Wout loads); bg owns 4 b's.
__global__ void outp_kernel(const float* __restrict__ Wout)
{
    __shared__ float c_sm[32 * 64];   // [b][kl] : 8 KB
    int cg = blockIdx.x, ks = blockIdx.y;
    int tid = threadIdx.x;
    int lane = tid & 31, bg = tid >> 5;

    // stage ctx slice: all 32 b's, k range ks*64..+64
    for (int k = tid; k < 32 * 64; k += 256) {
        int bb = k >> 6, kl = k & 63;
        c_sm[k] = g_CTX[(size_t)bb * (H_ * D_) + ks * 64 + kl];
    }
    __syncthreads();

    // Wout float4 pointer: row i (k), cols cg*128 + 4*lane
    const float4* wp = reinterpret_cast<const float4*>(
        Wout + ((size_t)ks * 64) * AU_) + cg * 32 + lane;

    float4 acc0 = make_float4(0.f, 0.f, 0.f, 0.f);
    float4 acc1 = make_float4(0.f, 0.f, 0.f, 0.f);
    float4 acc2 = make_float4(0.f, 0.f, 0.f, 0.f);
    float4 acc3 = make_float4(0.f, 0.f, 0.f, 0.f);
    const float* c0 = c_sm + (4 * bg + 0) * 64;
    const float* c1 = c_sm + (4 * bg + 1) * 64;
    const float* c2 = c_sm + (4 * bg + 2) * 64;
    const float* c3 = c_sm + (4 * bg + 3) * 64;

    #pragma unroll 8
    for (int i = 0; i < 64; i++) {
        float4 w = wp[(size_t)i * (AU_ / 4)];
        float a = c0[i], bb = c1[i], cc = c2[i], dd = c3[i];
        acc0.x += a * w.x; acc0.y += a * w.y; acc0.z += a * w.z; acc0.w += a * w.w;
        acc1.x += bb * w.x; acc1.y += bb * w.y; acc1.z += bb * w.z; acc1.w += bb * w.w;
        acc2.x += cc * w.x; acc2.y += cc * w.y; acc2.z += cc * w.z; acc2.w += cc * w.w;
        acc3.x += dd * w.x; acc3.y += dd * w.y; acc3.z += dd * w.z; acc3.w += dd * w.w;
    }

    float4* op = reinterpret_cast<float4*>(
        g_OUTP + (size_t)ks * B_ * AU_) + cg * 32 + lane;
    op[(size_t)(4 * bg + 0) * (AU_ / 4)] = acc0;
    op[(size_t)(4 * bg + 1) * (AU_ / 4)] = acc1;
    op[(size_t)(4 * bg + 2) * (AU_ / 4)] = acc2;
    op[(size_t)(4 * bg + 3) * (AU_ / 4)] = acc3;
}

// ---------------- kernel 4: out final ----------------------------------------
__global__ void outf_kernel(const float* __restrict__ bout,
                            float* __restrict__ out)
{
    int b = blockIdx.x, t = threadIdx.x;   // 32 x 512
    float v = bout[t];
    #pragma unroll 8
    for (int s = 0; s < KS_; s++)
        v += g_OUTP[((size_t)s * B_ + b) * AU_ + t];
    out[(size_t)b * AU_ + t] = v;
}

// ---------------------------------------------------------------------------
extern "C" void kernel_launch(void* const* d_in, const int* in_sizes, int n_in,
                              void* d_out, int out_size)
{
    const float* dec   = (const float*)d_in[0];
    const float* enc   = (const float*)d_in[1];
    const float* prev  = (const float*)d_in[2];
    const float* Wphi  = (const float*)d_in[3];
    const float* bphi  = (const float*)d_in[4];
    const float* Wpsi  = (const float*)d_in[5];
    // d_in[6] = bpsi: constant along u per (b,h) -> softmax-invariant, unused
    const float* ck    = (const float*)d_in[7];
    const float* Wloc  = (const float*)d_in[8];
    const float* Wout  = (const float*)d_in[9];
    const float* bout  = (const float*)d_in[10];
    float* out = (float*)d_out;

    prep_kernel<<<256, 256>>>(dec, Wphi, bphi, Wpsi, ck, Wloc, prev); // idx 0
    fused_kernel<<<dim3(NC, B_), 256, SMEM_F_BYTES>>>(enc);           // idx 1
    norm_kernel<<<192, 512>>>(out);                                   // idx 2
    outp_kernel<<<dim3(4, KS_), 256>>>(Wout);                         // idx 3 <- profiled
    outf_kernel<<<B_, 512>>>(bout, out);                              // idx 4
}

// round 11
// speedup vs baseline: 2.5948x; 1.0266x over previous
#include <cuda_runtime.h>
#include <cuda_bf16.h>
#include <cstdint>

// Problem constants
#define B_    32
#define U_    4096
#define D_    512
#define H_    4
#define HD_   128
#define CK_   31
#define CF_   32
#define AU_   512

#define UC    128            // u rows per CTA chunk
#define NC    (U_ / UC)      // 32 chunks per batch
#define ST    8              // rows per pipeline stage
#define NSUB  (UC / ST)      // 16
#define KS_   64             // k-slices for the out GEMM (depth 32 each)

// ---------------- scratch (device globals) ----------------------------------
__device__ float g_V[B_ * H_ * D_];
__device__ float g_LB[(size_t)B_ * U_ * H_];                // location bias [b][u][h]
__device__ float g_P[(size_t)B_ * U_ * H_];                 // exp(energy), [b][u][h]
__device__ float g_CTXP[(size_t)B_ * NC * H_ * D_];         // per-chunk ctx partials
__device__ float g_SP[B_ * NC * H_];                        // per-chunk sum of p
__device__ float g_CTX[B_ * H_ * D_];                       // normalized context
__device__ float g_OUTP[KS_ * B_ * AU_];                    // out GEMM partials

// ---------------- PTX helpers -----------------------------------------------
__device__ __forceinline__ uint32_t smem_u32(const void* p) {
    uint32_t a;
    asm("{ .reg .u64 t; cvta.to.shared.u64 t, %1; cvt.u32.u64 %0, t; }"
        : "=r"(a) : "l"(p));
    return a;
}
__device__ __forceinline__ void cp_async16(uint32_t dst, const void* src) {
    asm volatile("cp.async.cg.shared.global [%0], [%1], 16;"
                 :: "r"(dst), "l"(src) : "memory");
}
__device__ __forceinline__ void cp_commit() {
    asm volatile("cp.async.commit_group;" ::: "memory");
}
template <int N>
__device__ __forceinline__ void cp_wait() {
    asm volatile("cp.async.wait_group %0;" :: "n"(N) : "memory");
}
__device__ __forceinline__ void fma2(unsigned long long& d,
                                     unsigned long long a,
                                     unsigned long long b) {
    asm("fma.rn.f32x2 %0, %1, %2, %0;" : "+l"(d) : "l"(a), "l"(b));
}
__device__ __forceinline__ unsigned long long pack2(float lo, float hi) {
    unsigned long long r;
    asm("mov.b64 %0, {%1, %2};" : "=l"(r) : "f"(lo), "f"(hi));
    return r;
}
__device__ __forceinline__ float2 unpack2(unsigned long long v) {
    float2 r;
    asm("mov.b64 {%0, %1}, %2;" : "=f"(r.x), "=f"(r.y) : "l"(v));
    return r;
}

// ---------------- kernel 0: prep = phiv (blocks 0..127) + lb (128..255) -----
__global__ void prep_kernel(const float* __restrict__ dec,
                            const float* __restrict__ Wphi,
                            const float* __restrict__ bphi,
                            const float* __restrict__ Wpsi,
                            const float* __restrict__ ck,
                            const float* __restrict__ Wloc,
                            const float* __restrict__ prev)
{
    __shared__ float sm[1184];
    int bx = blockIdx.x;
    int tid = threadIdx.x;   // 256

    if (bx < 128) {
        float* dec_sm   = sm;            // 512
        float* phi_part = sm + 512;      // 2*128
        float* phi_sm   = sm + 768;      // 128
        int b = bx >> 2, h = bx & 3;

        for (int i = tid; i < D_; i += 256) dec_sm[i] = dec[(size_t)b * D_ + i];
        __syncthreads();

        {
            int k = tid & 127, sl = tid >> 7;
            const float* w = Wphi + (size_t)h * D_ * HD_ + (size_t)sl * 256 * HD_ + k;
            const float* ds = dec_sm + sl * 256;
            float a0 = 0.f, a1 = 0.f, a2 = 0.f, a3 = 0.f;
            #pragma unroll 8
            for (int d = 0; d < 256; d += 4) {
                a0 += ds[d + 0] * w[(size_t)(d + 0) * HD_];
                a1 += ds[d + 1] * w[(size_t)(d + 1) * HD_];
                a2 += ds[d + 2] * w[(size_t)(d + 2) * HD_];
                a3 += ds[d + 3] * w[(size_t)(d + 3) * HD_];
            }
            phi_part[sl * 128 + k] = (a0 + a1) + (a2 + a3);
        }
        __syncthreads();
        if (tid < HD_)
            phi_sm[tid] = phi_part[tid] + phi_part[128 + tid] + bphi[h * HD_ + tid];
        __syncthreads();

        for (int e = tid; e < D_; e += 256) {
            const float4* wp = reinterpret_cast<const float4*>(
                Wpsi + ((size_t)h * D_ + e) * HD_);
            float vv = 0.f;
            #pragma unroll 8
            for (int k4 = 0; k4 < HD_ / 4; k4++) {
                float4 ww = wp[k4];
                vv += ww.x * phi_sm[4 * k4 + 0] + ww.y * phi_sm[4 * k4 + 1]
                    + ww.z * phi_sm[4 * k4 + 2] + ww.w * phi_sm[4 * k4 + 3];
            }
            g_V[(size_t)bx * D_ + e] = vv;
        }
    } else {
        float* prevs = sm;               // 1024 + 30
        float* keffs = sm + 1056;        // 124
        int idx = bx - 128;
        int z = idx & 3, b = idx >> 2;
        int ubase = z * 1024;

        if (tid < CK_ * H_) {
            int k = tid >> 2, h = tid & 3;
            float s = 0.f;
            #pragma unroll
            for (int f = 0; f < CF_; f++)
                s += ck[k * CF_ + f] * Wloc[f * H_ + h];
            keffs[tid] = s;
        }
        for (int i = tid; i < 1024 + CK_ - 1; i += 256) {
            int gu = ubase + i - 15;
            prevs[i] = (gu >= 0 && gu < U_) ? prev[(size_t)b * U_ + gu] : 0.f;
        }
        __syncthreads();

        float4* outp = reinterpret_cast<float4*>(
            g_LB + ((size_t)b * U_ + ubase) * H_);
        #pragma unroll
        for (int q = 0; q < 4; q++) {
            int ul = tid + 256 * q;
            float l0 = 0.f, l1 = 0.f, l2 = 0.f, l3 = 0.f;
            #pragma unroll
            for (int k = 0; k < CK_; k++) {
                float pv = prevs[ul + k];
                l0 += pv * keffs[k * H_ + 0];
                l1 += pv * keffs[k * H_ + 1];
                l2 += pv * keffs[k * H_ + 2];
                l3 += pv * keffs[k * H_ + 3];
            }
            outp[ul] = make_float4(l0, l1, l2, l3);
        }
    }
}

// ---------------- kernel 1: fused energy+exp+context ------------------------
#define SMEM_F_FLOATS 11264
#define SMEM_F_BYTES (SMEM_F_FLOATS * 4)

__global__ void __launch_bounds__(256, 4)
fused_kernel(const float* __restrict__ enc)
{
    extern __shared__ float smem[];
    float* tiles  = smem;
    float* ctxred = smem + 8192;
    float* pall   = smem + 10240;
    float* lbs    = smem + 10752;

    int tid  = threadIdx.x;
    int warp = tid >> 5, lane = tid & 31;
    int h = warp & 3, rg = warp >> 2;
    int b  = blockIdx.y;
    int u0 = blockIdx.x * UC;

    const float* enc_base = enc + ((size_t)b * U_ + u0) * D_;
    uint32_t tiles_s = smem_u32(tiles);

    #pragma unroll
    for (int s = 0; s < 2; s++) {
        uint32_t dst = tiles_s + s * (ST * D_ * 4);
        const float* src = enc_base + s * ST * D_;
        #pragma unroll
        for (int q = 0; q < 4; q++) {
            int idx = tid + 256 * q;
            cp_async16(dst + idx * 16, src + idx * 4);
        }
        cp_commit();
    }

    #pragma unroll
    for (int q = 0; q < 2; q++) {
        int idx = tid + 256 * q;
        lbs[idx] = g_LB[((size_t)b * U_ + u0) * H_ + idx];
    }

    ulonglong2 v2[4];
    {
        const ulonglong2* vp = reinterpret_cast<const ulonglong2*>(
            g_V + (size_t)(b * H_ + h) * D_);
        #pragma unroll
        for (int i = 0; i < 4; i++) v2[i] = vp[lane + 32 * i];
    }

    unsigned long long ctx2[8];
    #pragma unroll
    for (int i = 0; i < 8; i++) ctx2[i] = 0ull;

    for (int s = 0; s < NSUB; s++) {
        if (s < NSUB - 1) cp_wait<1>(); else cp_wait<0>();
        __syncthreads();
        const float* tile = tiles + (s & 1) * (ST * D_);

        #pragma unroll
        for (int t = 0; t < 4; t++) {
            int r = rg * 4 + t;
            int uu = s * ST + r;
            const ulonglong2* row =
                reinterpret_cast<const ulonglong2*>(tile + r * D_);
            ulonglong2 X[4];
            #pragma unroll
            for (int i = 0; i < 4; i++) X[i] = row[lane + 32 * i];

            unsigned long long a2 = 0ull;
            #pragma unroll
            for (int i = 0; i < 4; i++) {
                fma2(a2, X[i].x, v2[i].x);
                fma2(a2, X[i].y, v2[i].y);
            }
            float2 f = unpack2(a2);
            float a = f.x + f.y;
            #pragma unroll
            for (int off = 16; off; off >>= 1)
                a += __shfl_xor_sync(0xffffffffu, a, off);
            float p = __expf(a + lbs[uu * H_ + h]);
            if (lane == 0) pall[uu * H_ + h] = p;
            unsigned long long pp = pack2(p, p);
            #pragma unroll
            for (int i = 0; i < 4; i++) {
                fma2(ctx2[2 * i + 0], X[i].x, pp);
                fma2(ctx2[2 * i + 1], X[i].y, pp);
            }
        }
        __syncthreads();

        if (s + 2 < NSUB) {
            uint32_t dst = tiles_s + (s & 1) * (ST * D_ * 4);
            const float* src = enc_base + (s + 2) * ST * D_;
            #pragma unroll
            for (int q = 0; q < 4; q++) {
                int idx = tid + 256 * q;
                cp_async16(dst + idx * 16, src + idx * 4);
            }
            cp_commit();
        }
    }

    float4 c[4];
    #pragma unroll
    for (int i = 0; i < 4; i++) {
        float2 lo = unpack2(ctx2[2 * i + 0]);
        float2 hi = unpack2(ctx2[2 * i + 1]);
        c[i] = make_float4(lo.x, lo.y, hi.x, hi.y);
    }
    float4* cr = reinterpret_cast<float4*>(ctxred + h * D_);
    if (rg == 0) {
        #pragma unroll
        for (int i = 0; i < 4; i++) cr[lane + 32 * i] = c[i];
    }
    __syncthreads();
    if (rg == 1) {
        #pragma unroll
        for (int i = 0; i < 4; i++) {
            float4 o = cr[lane + 32 * i];
            o.x += c[i].x; o.y += c[i].y; o.z += c[i].z; o.w += c[i].w;
            cr[lane + 32 * i] = o;
        }
    }
    __syncthreads();

    size_t chunk = (size_t)b * NC + blockIdx.x;

    #pragma unroll
    for (int q = 0; q < 8; q++) {
        int idx = tid + 256 * q;
        g_CTXP[chunk * (H_ * D_) + idx] = ctxred[idx];
    }

    if (warp < H_) {
        float sp = pall[lane * H_ + warp] + pall[(lane + 32) * H_ + warp]
                 + pall[(lane + 64) * H_ + warp] + pall[(lane + 96) * H_ + warp];
        #pragma unroll
        for (int off = 16; off; off >>= 1)
            sp += __shfl_xor_sync(0xffffffffu, sp, off);
        if (lane == 0) g_SP[chunk * H_ + warp] = sp;
    }

    #pragma unroll
    for (int jj = 0; jj < 2; jj++) {
        int idx = tid + 256 * jj;
        g_P[((size_t)b * U_ + u0) * H_ + idx] = pall[idx];
    }
}

// ---------------- kernel 2: norm = combine (0..127) + aw (128..191) ---------
__global__ void norm_kernel(float* __restrict__ out)
{
    int bx = blockIdx.x;
    int tid = threadIdx.x;   // 512
    int warp = tid >> 5, lane = tid & 31;

    if (bx < 128) {
        int h = bx & 3, b = bx >> 2;
        __shared__ float S_sm;
        if (tid < 32) {
            float sc = g_SP[((size_t)b * NC + lane) * H_ + h];
            #pragma unroll
            for (int off = 16; off; off >>= 1)
                sc += __shfl_xor_sync(0xffffffffu, sc, off);
            if (lane == 0) S_sm = sc;
        }
        __syncthreads();
        float invS = 1.f / S_sm;

        const float* base = g_CTXP + (size_t)b * NC * H_ * D_ + h * D_ + tid;
        float a = 0.f;
        #pragma unroll 8
        for (int c = 0; c < NC; c++)
            a += base[(size_t)c * H_ * D_];
        g_CTX[(size_t)(b * H_ + h) * D_ + tid] = a * invS;
    } else {
        int q = bx - 128;        // 0..63
        int b = q >> 1, half = q & 1;
        __shared__ float S4[4];
        if (warp < 4) {
            float sc = g_SP[((size_t)b * NC + lane) * H_ + warp];
            #pragma unroll
            for (int off = 16; off; off >>= 1)
                sc += __shfl_xor_sync(0xffffffffu, sc, off);
            if (lane == 0) S4[warp] = 0.25f / sc;
        }
        __syncthreads();
        float i0 = S4[0], i1 = S4[1], i2 = S4[2], i3 = S4[3];

        const float4* p = reinterpret_cast<const float4*>(
            g_P + ((size_t)b * U_ + half * 2048) * H_);
        float* o = out + (size_t)B_ * AU_ + (size_t)b * U_ + half * 2048;
        #pragma unroll
        for (int k = 0; k < 4; k++) {
            int u = tid + 512 * k;
            float4 v = p[u];
            o[u] = v.x * i0 + v.y * i1 + v.z * i2 + v.w * i3;
        }
    }
}

// ---------------- kernel 3 (PROFILED): out GEMM partials --------------------
// grid (4 colgroups of 128, KS_=64 k-slices of 32), block 512 = 32 lanes x 16 bg.
// Lane owns 4 consecutive cols (float4 Wout loads); bg owns 2 b's.
__global__ void outp_kernel(const float* __restrict__ Wout)
{
    __shared__ float c_sm[32 * 32];   // [b][kl] : 4 KB
    int cg = blockIdx.x, ks = blockIdx.y;
    int tid = threadIdx.x;
    int lane = tid & 31, bg = tid >> 5;   // bg 0..15

    // stage ctx slice: all 32 b's, k range ks*32..+32
    for (int k = tid; k < 32 * 32; k += 512) {
        int bb = k >> 5, kl = k & 31;
        c_sm[k] = g_CTX[(size_t)bb * (H_ * D_) + ks * 32 + kl];
    }
    __syncthreads();

    const float4* wp = reinterpret_cast<const float4*>(
        Wout + ((size_t)ks * 32) * AU_) + cg * 32 + lane;

    float4 acc0 = make_float4(0.f, 0.f, 0.f, 0.f);
    float4 acc1 = make_float4(0.f, 0.f, 0.f, 0.f);
    const float* c0 = c_sm + (2 * bg + 0) * 32;
    const float* c1 = c_sm + (2 * bg + 1) * 32;

    #pragma unroll
    for (int i = 0; i < 32; i++) {
        float4 w = wp[(size_t)i * (AU_ / 4)];
        float a = c0[i], bb = c1[i];
        acc0.x += a * w.x;  acc0.y += a * w.y;
        acc0.z += a * w.z;  acc0.w += a * w.w;
        acc1.x += bb * w.x; acc1.y += bb * w.y;
        acc1.z += bb * w.z; acc1.w += bb * w.w;
    }

    float4* op = reinterpret_cast<float4*>(
        g_OUTP + (size_t)ks * B_ * AU_) + cg * 32 + lane;
    op[(size_t)(2 * bg + 0) * (AU_ / 4)] = acc0;
    op[(size_t)(2 * bg + 1) * (AU_ / 4)] = acc1;
}

// ---------------- kernel 4: out final ----------------------------------------
__global__ void outf_kernel(const float* __restrict__ bout,
                            float* __restrict__ out)
{
    int b = blockIdx.x, t = threadIdx.x;   // 32 x 512
    float v = bout[t];
    #pragma unroll 8
    for (int s = 0; s < KS_; s++)
        v += g_OUTP[((size_t)s * B_ + b) * AU_ + t];
    out[(size_t)b * AU_ + t] = v;
}

// ---------------------------------------------------------------------------
extern "C" void kernel_launch(void* const* d_in, const int* in_sizes, int n_in,
                              void* d_out, int out_size)
{
    const float* dec   = (const float*)d_in[0];
    const float* enc   = (const float*)d_in[1];
    const float* prev  = (const float*)d_in[2];
    const float* Wphi  = (const float*)d_in[3];
    const float* bphi  = (const float*)d_in[4];
    const float* Wpsi  = (const float*)d_in[5];
    // d_in[6] = bpsi: constant along u per (b,h) -> softmax-invariant, unused
    const float* ck    = (const float*)d_in[7];
    const float* Wloc  = (const float*)d_in[8];
    const float* Wout  = (const float*)d_in[9];
    const float* bout  = (const float*)d_in[10];
    float* out = (float*)d_out;

    prep_kernel<<<256, 256>>>(dec, Wphi, bphi, Wpsi, ck, Wloc, prev); // idx 0
    fused_kernel<<<dim3(NC, B_), 256, SMEM_F_BYTES>>>(enc);           // idx 1
    norm_kernel<<<192, 512>>>(out);                                   // idx 2
    outp_kernel<<<dim3(4, KS_), 512>>>(Wout);                         // idx 3 <- profiled
    outf_kernel<<<B_, 512>>>(bout, out);                              // idx 4
}